// round 15
// baseline (speedup 1.0000x reference)
#include <cuda_runtime.h>
#include <cuda_bf16.h>
#include <math.h>

#define Nn   2048
#define FIN  768
#define H1d  512
#define H2d  256
#define LCd  256
#define MAXK 512
#define CAP  1024
#define ELLW 64
#define CAPBIG 2100000
#define NBLK 148

// ------------------------- device scratch (no allocs allowed) ---------------
__device__ float g_S  [2*Nn*H1d];
__device__ float g_Hid[2*Nn*H1d];
__device__ float g_Q  [2*Nn*H1d];
__device__ float g_Kb [2*LCd*H1d];
__device__ float g_Vb [2*LCd*H1d];
__device__ float g_att[4*Nn*LCd];
__device__ float g_O  [2*Nn*H1d];
__device__ float g_Mh [2*Nn*H1d];
__device__ float g_T  [4*Nn*H2d];
__device__ float g_mu  [Nn*H2d];
__device__ float g_lv  [Nn*H2d];
__device__ float g_mupr[Nn*H2d];
__device__ float g_lvpr[Nn*H2d];
__device__ unsigned short g_zhi[Nn*H2d];
__device__ unsigned short g_zlo[Nn*H2d];
__device__ float g_ns2[Nn*H2d];
__device__ unsigned g_keys[(size_t)Nn*Nn];
__device__ unsigned g_hist1[65536];
__device__ unsigned g_hist2[65536];
__device__ unsigned g_hist3[65536];
__device__ unsigned g_hist4[65536];
__device__ double   g_sums[4];
__device__ unsigned g_meta[8];
__device__ unsigned g_xstar;
__device__ unsigned g_bar;
__device__ int      g_candCount;
__device__ int      g_candCount2;
__device__ unsigned long long g_candBig[CAPBIG];
__device__ unsigned long long g_cand[CAP];
__device__ int      g_sel[MAXK];
__device__ int   g_nnz [2][Nn];
__device__ int   g_cols[2][Nn*ELLW];
__device__ float g_vals[2][Nn*ELLW];

__device__ __forceinline__ float leakyf(float x) { return x >= 0.f ? x : 0.01f * x; }

struct GPtrs  { const float* A[4]; const float* B[4]; float* C[4]; };
struct SpArgs { const float* X[4]; float* Y[4]; int wh[4]; };

// ------------------------- mma helpers ---------------------------------------
__device__ __forceinline__ unsigned sptr(const void* p) {
    return (unsigned)__cvta_generic_to_shared(p);
}
__device__ __forceinline__ void ldsm4(unsigned* r, unsigned addr) {
    asm volatile("ldmatrix.sync.aligned.m8n8.x4.shared.b16 {%0,%1,%2,%3},[%4];"
                 : "=r"(r[0]), "=r"(r[1]), "=r"(r[2]), "=r"(r[3]) : "r"(addr));
}
__device__ __forceinline__ void ldsm4t(unsigned* r, unsigned addr) {
    asm volatile("ldmatrix.sync.aligned.m8n8.x4.trans.shared.b16 {%0,%1,%2,%3},[%4];"
                 : "=r"(r[0]), "=r"(r[1]), "=r"(r[2]), "=r"(r[3]) : "r"(addr));
}
__device__ __forceinline__ void mma16816(float* c, const unsigned* a, const unsigned* b) {
    asm volatile("mma.sync.aligned.m16n8k16.row.col.f32.bf16.bf16.f32 "
                 "{%0,%1,%2,%3},{%4,%5,%6,%7},{%8,%9},{%0,%1,%2,%3};"
                 : "+f"(c[0]), "+f"(c[1]), "+f"(c[2]), "+f"(c[3])
                 : "r"(a[0]), "r"(a[1]), "r"(a[2]), "r"(a[3]), "r"(b[0]), "r"(b[1]));
}
__device__ __forceinline__ uint2 cvtf4(float4 v) {
    __nv_bfloat162 lo = __float22bfloat162_rn(make_float2(v.x, v.y));
    __nv_bfloat162 hi = __float22bfloat162_rn(make_float2(v.z, v.w));
    uint2 u; u.x = *(unsigned*)&lo; u.y = *(unsigned*)&hi; return u;
}
__device__ __forceinline__ void splitf4(float4 v, uint2& H, uint2& L) {
    __nv_bfloat16 h0 = __float2bfloat16(v.x), h1 = __float2bfloat16(v.y);
    __nv_bfloat16 h2 = __float2bfloat16(v.z), h3 = __float2bfloat16(v.w);
    __nv_bfloat16 l0 = __float2bfloat16(v.x - __bfloat162float(h0));
    __nv_bfloat16 l1 = __float2bfloat16(v.y - __bfloat162float(h1));
    __nv_bfloat16 l2 = __float2bfloat16(v.z - __bfloat162float(h2));
    __nv_bfloat16 l3 = __float2bfloat16(v.w - __bfloat162float(h3));
    H.x = (unsigned)*(unsigned short*)&h0 | ((unsigned)*(unsigned short*)&h1 << 16);
    H.y = (unsigned)*(unsigned short*)&h2 | ((unsigned)*(unsigned short*)&h3 << 16);
    L.x = (unsigned)*(unsigned short*)&l0 | ((unsigned)*(unsigned short*)&l1 << 16);
    L.y = (unsigned)*(unsigned short*)&l2 | ((unsigned)*(unsigned short*)&l3 << 16);
}

// -- batched bf16 tensor-core GEMM, 128x64 tile, frag-pipelined, overlay epi --
template<int TRANSB>
__global__ void __launch_bounds__(256) gemmT_k(GPtrs p, int K, int lda, int ldb, int ldc,
                                               float alpha, int act)
{
    constexpr int BR = TRANSB ? 64 : 32;
    constexpr int BC = TRANSB ? 40 : 72;
    constexpr int AS_B = 2 * 128 * 40 * 2;
    constexpr int BS_B = 2 * BR * BC * 2;
    constexpr int CS_B = 128 * 68 * 4;
    constexpr int SM_B = (AS_B + BS_B > CS_B) ? (AS_B + BS_B) : CS_B;
    __shared__ __align__(16) char smraw[SM_B];
    typedef unsigned short ArrA[128][40];
    typedef unsigned short ArrB[BR][BC];
    ArrA* As = reinterpret_cast<ArrA*>(smraw);
    ArrB* Bs = reinterpret_cast<ArrB*>(smraw + AS_B);
    float (*Cs)[68] = reinterpret_cast<float(*)[68]>(smraw);

    const float* __restrict__ A = p.A[blockIdx.z];
    const float* __restrict__ B = p.B[blockIdx.z];
    float* __restrict__ C = p.C[blockIdx.z];
    const int bm = blockIdx.y * 128, bn = blockIdx.x * 64;
    const int t = threadIdx.x, lane = t & 31, wid = t >> 5;
    const int wy = TRANSB ? (wid >> 1) : (wid & 1);
    const int wx = TRANSB ? (wid & 1)  : (wid >> 1);

    float4 aR[4], bR[2];
    auto loadG = [&](int k0) {
        #pragma unroll
        for (int i = 0; i < 4; i++) {
            int l = t + i * 256;
            aR[i] = *(const float4*)&A[(size_t)(bm + (l >> 3)) * lda + k0 + (l & 7) * 4];
        }
        #pragma unroll
        for (int i = 0; i < 2; i++) {
            int l = t + i * 256;
            if (TRANSB)
                bR[i] = *(const float4*)&B[(size_t)(bn + (l >> 3)) * ldb + k0 + (l & 7) * 4];
            else
                bR[i] = *(const float4*)&B[(size_t)(k0 + (l >> 4)) * ldb + bn + (l & 15) * 4];
        }
    };
    auto storeS = [&](int buf) {
        #pragma unroll
        for (int i = 0; i < 4; i++) {
            int l = t + i * 256;
            *(uint2*)&As[buf][l >> 3][(l & 7) * 4] = cvtf4(aR[i]);
        }
        #pragma unroll
        for (int i = 0; i < 2; i++) {
            int l = t + i * 256;
            if (TRANSB) *(uint2*)&Bs[buf][l >> 3][(l & 7) * 4] = cvtf4(bR[i]);
            else        *(uint2*)&Bs[buf][l >> 4][(l & 15) * 4] = cvtf4(bR[i]);
        }
    };

    unsigned afr[2][2][4], bfr[2][4][2];
    auto loadFrag = [&](int c_, int ks, int slot) {
        if (TRANSB) {
            #pragma unroll
            for (int tn = 0; tn < 2; tn++) {
                int row = wy * 32 + tn * 16 + (lane & 15);
                int kof = ks + ((lane >> 4) << 3);
                ldsm4(afr[slot][tn], sptr(&As[c_][row][kof]));
            }
            #pragma unroll
            for (int g = 0; g < 2; g++) {
                int row = wx * 32 + g * 16 + ((lane >> 4) << 3) + (lane & 7);
                int kof = ks + (((lane >> 3) & 1) << 3);
                unsigned r[4];
                ldsm4(r, sptr(&Bs[c_][row][kof]));
                bfr[slot][2*g][0] = r[0]; bfr[slot][2*g][1] = r[1];
                bfr[slot][2*g+1][0] = r[2]; bfr[slot][2*g+1][1] = r[3];
            }
        } else {
            #pragma unroll
            for (int tn = 0; tn < 2; tn++) {   // opA = B^T via trans LDSM
                int krow = ks + ((lane >> 4) << 3) + (lane & 7);
                int nof  = wy * 32 + tn * 16 + (((lane >> 3) & 1) << 3);
                ldsm4t(afr[slot][tn], sptr(&Bs[c_][krow][nof]));
            }
            #pragma unroll
            for (int g = 0; g < 2; g++) {      // opB = A^T via non-trans LDSM
                int row = wx * 32 + g * 16 + ((lane >> 4) << 3) + (lane & 7);
                int kof = ks + (((lane >> 3) & 1) << 3);
                unsigned r[4];
                ldsm4(r, sptr(&As[c_][row][kof]));
                bfr[slot][2*g][0] = r[0]; bfr[slot][2*g][1] = r[1];
                bfr[slot][2*g+1][0] = r[2]; bfr[slot][2*g+1][1] = r[3];
            }
        }
    };

    float acc[2][4][4] = {};
    auto mmaAll = [&](int slot) {
        #pragma unroll
        for (int tn = 0; tn < 2; tn++)
            #pragma unroll
            for (int tb = 0; tb < 4; tb++)
                mma16816(acc[tn][tb], afr[slot][tn], bfr[slot][tb]);
    };

    loadG(0); storeS(0); __syncthreads();
    loadFrag(0, 0, 0);
    int cur = 0;
    for (int k0 = 0; k0 < K; k0 += 32) {
        const int kn = k0 + 32;
        if (kn < K) loadG(kn);
        loadFrag(cur, 16, 1);
        mmaAll(0);
        if (kn < K) storeS(cur ^ 1);
        mmaAll(1);
        __syncthreads();
        cur ^= 1;
        if (kn < K) loadFrag(cur, 0, 0);
    }

    const int g = lane >> 2, tg = lane & 3;
    #pragma unroll
    for (int tn = 0; tn < 2; tn++)
        #pragma unroll
        for (int tb = 0; tb < 4; tb++)
            #pragma unroll
            for (int r = 0; r < 4; r++) {
                int rr = wy * 32 + tn * 16 + g + ((r >> 1) << 3);
                int cc = wx * 32 + tb * 8 + 2 * tg + (r & 1);
                if (TRANSB) Cs[rr][cc] = acc[tn][tb][r];
                else        Cs[cc][rr] = acc[tn][tb][r];
            }
    __syncthreads();
    #pragma unroll
    for (int i = 0; i < 8; i++) {
        int l = t + i * 256;
        int row = l >> 4, nq = (l & 15) * 4;
        float4 v;
        float* pv = &v.x;
        #pragma unroll
        for (int j = 0; j < 4; j++) {
            float w = Cs[row][nq + j] * alpha;
            if (act) w = leakyf(w);
            pv[j] = w;
        }
        *(float4*)&C[(size_t)(bm + row) * ldc + bn + nq] = v;
    }
}

// ---- ns2 GEMM: full-split bf16 (A=hi+lo, B=hi+lo, 3 mma) -> ~1e-5 rel error -
__global__ void __launch_bounds__(256) gemmNS_k(const float* __restrict__ A,
                                                const float* __restrict__ B,
                                                float* __restrict__ C,
                                                int K, int lda, int ldb, int ldc)
{
    constexpr int AH_B = 2 * 128 * 40 * 2;
    constexpr int BH_B = 2 * 32 * 72 * 2;
    __shared__ __align__(16) char smraw[2 * AH_B + 2 * BH_B];
    typedef unsigned short ArrA[128][40];
    typedef unsigned short ArrB[32][72];
    ArrA* Ah = reinterpret_cast<ArrA*>(smraw);
    ArrA* Al = reinterpret_cast<ArrA*>(smraw + AH_B);
    ArrB* Bh = reinterpret_cast<ArrB*>(smraw + 2 * AH_B);
    ArrB* Bl = reinterpret_cast<ArrB*>(smraw + 2 * AH_B + BH_B);
    float (*Cs)[68] = reinterpret_cast<float(*)[68]>(smraw);

    const int bm = blockIdx.y * 128, bn = blockIdx.x * 64;
    const int t = threadIdx.x, lane = t & 31, wid = t >> 5;
    const int wy = wid & 1, wx = wid >> 1;

    float4 aR[4], bR[2];
    auto loadG = [&](int k0) {
        #pragma unroll
        for (int i = 0; i < 4; i++) {
            int l = t + i * 256;
            aR[i] = *(const float4*)&A[(size_t)(bm + (l >> 3)) * lda + k0 + (l & 7) * 4];
        }
        #pragma unroll
        for (int i = 0; i < 2; i++) {
            int l = t + i * 256;
            bR[i] = *(const float4*)&B[(size_t)(k0 + (l >> 4)) * ldb + bn + (l & 15) * 4];
        }
    };
    auto storeS = [&](int buf) {
        #pragma unroll
        for (int i = 0; i < 4; i++) {
            int l = t + i * 256;
            uint2 H, L; splitf4(aR[i], H, L);
            *(uint2*)&Ah[buf][l >> 3][(l & 7) * 4] = H;
            *(uint2*)&Al[buf][l >> 3][(l & 7) * 4] = L;
        }
        #pragma unroll
        for (int i = 0; i < 2; i++) {
            int l = t + i * 256;
            uint2 H, L; splitf4(bR[i], H, L);
            *(uint2*)&Bh[buf][l >> 4][(l & 15) * 4] = H;
            *(uint2*)&Bl[buf][l >> 4][(l & 15) * 4] = L;
        }
    };

    loadG(0); storeS(0); __syncthreads();

    float acc[2][4][4] = {};
    int cur = 0;
    for (int k0 = 0; k0 < K; k0 += 32) {
        const int kn = k0 + 32;
        if (kn < K) loadG(kn);
        #pragma unroll
        for (int ks = 0; ks < 32; ks += 16) {
            unsigned ah[2][4], al[2][4], bh[4][2], bl[4][2];
            #pragma unroll
            for (int tn = 0; tn < 2; tn++) {
                int krow = ks + ((lane >> 4) << 3) + (lane & 7);
                int nof  = wy * 32 + tn * 16 + (((lane >> 3) & 1) << 3);
                ldsm4t(ah[tn], sptr(&Bh[cur][krow][nof]));
                ldsm4t(al[tn], sptr(&Bl[cur][krow][nof]));
            }
            #pragma unroll
            for (int g = 0; g < 2; g++) {
                int row = wx * 32 + g * 16 + ((lane >> 4) << 3) + (lane & 7);
                int kof = ks + (((lane >> 3) & 1) << 3);
                unsigned r[4];
                ldsm4(r, sptr(&Ah[cur][row][kof]));
                bh[2*g][0] = r[0]; bh[2*g][1] = r[1];
                bh[2*g+1][0] = r[2]; bh[2*g+1][1] = r[3];
                ldsm4(r, sptr(&Al[cur][row][kof]));
                bl[2*g][0] = r[0]; bl[2*g][1] = r[1];
                bl[2*g+1][0] = r[2]; bl[2*g+1][1] = r[3];
            }
            #pragma unroll
            for (int tn = 0; tn < 2; tn++)
                #pragma unroll
                for (int tb = 0; tb < 4; tb++) {
                    mma16816(acc[tn][tb], ah[tn], bh[tb]);
                    mma16816(acc[tn][tb], ah[tn], bl[tb]);
                    mma16816(acc[tn][tb], al[tn], bh[tb]);
                }
        }
        if (kn < K) storeS(cur ^ 1);
        __syncthreads();
        cur ^= 1;
    }

    const int g = lane >> 2, tg = lane & 3;
    #pragma unroll
    for (int tn = 0; tn < 2; tn++)
        #pragma unroll
        for (int tb = 0; tb < 4; tb++)
            #pragma unroll
            for (int r = 0; r < 4; r++) {
                int rr = wy * 32 + tn * 16 + g + ((r >> 1) << 3);
                int cc = wx * 32 + tb * 8 + 2 * tg + (r & 1);
                Cs[cc][rr] = acc[tn][tb][r];
            }
    __syncthreads();
    #pragma unroll
    for (int i = 0; i < 8; i++) {
        int l = t + i * 256;
        int row = l >> 4, nq = (l & 15) * 4;
        float4 v;
        float* pv = &v.x;
        #pragma unroll
        for (int j = 0; j < 4; j++)
            pv[j] = leakyf(Cs[row][nq + j]);
        *(float4*)&C[(size_t)(bm + row) * ldc + bn + nq] = v;
    }
}

// ----- ELL build (warp per row) + absorbed scratch zeroing + x* search -------
__global__ void csrB_k(const float* __restrict__ a0, const float* __restrict__ a1)
{
    // zero slice of hists (512 blocks x 128 entries each per hist)
    const int lb = blockIdx.y * gridDim.x + blockIdx.x;   // 0..511
    {
        int i = lb * 128 + (threadIdx.x & 127);
        if (threadIdx.x < 128) { g_hist1[i] = 0; g_hist2[i] = 0; }
        else                   { g_hist3[i] = 0; g_hist4[i] = 0; }
    }
    if (lb == 0) {
        if (threadIdx.x < 4) g_sums[threadIdx.x] = 0.0;
        if (threadIdx.x >= 4 && threadIdx.x < 12) g_meta[threadIdx.x - 4] = 0u;
        if (threadIdx.x == 12) { g_candCount = 0; g_candCount2 = 0; g_bar = 0u; }
        if (threadIdx.x == 13) {
            unsigned lo = __float_as_uint(8.0f), hi = __float_as_uint(24.0f);
            while (lo < hi) {
                unsigned mid = lo + (hi - lo) / 2;
                float x = __uint_as_float(mid);
                float p = 1.f / (1.f + expf(-x));
                if (p == 1.0f) hi = mid; else lo = mid + 1;
            }
            g_xstar = lo;
        }
    }

    const int which = blockIdx.y;
    const float* adjM = which ? a1 : a0;
    int row  = blockIdx.x * (blockDim.x >> 5) + (threadIdx.x >> 5);
    int lane = threadIdx.x & 31;
    if (row >= Nn) return;
    const float* r = adjM + (size_t)row * Nn;
    int cnt = 0;
    for (int c0 = 0; c0 < Nn; c0 += 32) {
        float v = r[c0 + lane];
        unsigned m = __ballot_sync(0xffffffffu, v != 0.f);
        if (v != 0.f) {
            int pos = cnt + __popc(m & ((1u << lane) - 1u));
            if (pos < ELLW) {
                g_cols[which][row * ELLW + pos] = c0 + lane;
                g_vals[which][row * ELLW + pos] = v;
            }
        }
        cnt += __popc(m);
    }
    if (lane == 0) g_nnz[which][row] = cnt > ELLW ? ELLW : cnt;
}

// ----------- batched SpMM: Y[row, :] = leaky(sum a_rj X[j, :]), float4 -------
__global__ void spmmB_k(SpArgs a, int C)
{
    const int b   = blockIdx.y;
    const int row = blockIdx.x;
    const int which = a.wh[b];
    const float* __restrict__ X = a.X[b];
    float* __restrict__ Y = a.Y[b];
    __shared__ int   soff[ELLW];
    __shared__ float sv[ELLW];
    const int cnt = g_nnz[which][row];
    const int t = threadIdx.x;
    if (t < ELLW && t < cnt) {
        soff[t] = g_cols[which][row * ELLW + t] * C;
        sv[t]   = g_vals[which][row * ELLW + t];
    }
    __syncthreads();
    const int c = t * 4;
    float4 acc = {0.f, 0.f, 0.f, 0.f};
    #pragma unroll 8
    for (int k = 0; k < cnt; k++) {
        float4 xv = *(const float4*)&X[soff[k] + c];
        float s = sv[k];
        acc.x += s * xv.x; acc.y += s * xv.y;
        acc.z += s * xv.z; acc.w += s * xv.w;
    }
    float4 o = {leakyf(acc.x), leakyf(acc.y), leakyf(acc.z), leakyf(acc.w)};
    *(float4*)&Y[(size_t)row * C + c] = o;
}

// ------------------------- softmax over rows of 256 --------------------------
__global__ void softmax_k(float* __restrict__ s)
{
    const int row = blockIdx.x;
    float* p = s + (size_t)row * 256;
    const int t = threadIdx.x;
    __shared__ float red[256];
    float v = p[t];
    red[t] = v; __syncthreads();
    for (int st = 128; st > 0; st >>= 1) { if (t < st) red[t] = fmaxf(red[t], red[t + st]); __syncthreads(); }
    float mx = red[0]; __syncthreads();
    float e = expf(v - mx);
    red[t] = e; __syncthreads();
    for (int st = 128; st > 0; st >>= 1) { if (t < st) red[t] += red[t + st]; __syncthreads(); }
    p[t] = e / red[0];
}

// --- fused: z = eps*exp(0.5*lv)+mu (split to bf16 hi/lo) AND KLD reduction ---
__global__ void zkld_k(const float* __restrict__ eps)
{
    const int i = blockIdx.x * blockDim.x + threadIdx.x;
    float mupo = g_mu[i], lvpo = g_lv[i];
    float zv = eps[i] * expf(0.5f * lvpo) + mupo;
    __nv_bfloat16 h = __float2bfloat16(zv);
    __nv_bfloat16 l = __float2bfloat16(zv - __bfloat162float(h));
    g_zhi[i] = *(unsigned short*)&h;
    g_zlo[i] = *(unsigned short*)&l;
    float mupr = g_mupr[i], lvpr = g_lvpr[i];
    float d = mupr - mupo;
    float term = d * d * expf(-lvpr) + expf(lvpo - lvpr) - 1.f - (lvpo - lvpr);
    __shared__ float red[256];
    const int t = threadIdx.x;
    red[t] = term; __syncthreads();
    for (int st = 128; st > 0; st >>= 1) { if (t < st) red[t] += red[t + st]; __syncthreads(); }
    if (t == 0) atomicAdd(&g_sums[3], (double)red[0]);
}

// --- decoder: x = z z^T via split-bf16 tensor cores, frag-pipelined ----------
__global__ void __launch_bounds__(256) decoder_k(const float* __restrict__ labels)
{
    __shared__ unsigned short Zih[2][128][40];
    __shared__ unsigned short Zil[2][128][40];
    __shared__ unsigned short Zjh[2][64][40];
    __shared__ unsigned short Zjl[2][64][40];
    const int bi = blockIdx.y * 128, bj = blockIdx.x * 64;
    const int t = threadIdx.x, lane = t & 31, wid = t >> 5;
    const int wy = wid >> 1, wx = wid & 1;
    const float xstar = __uint_as_float(g_xstar);

    uint4 ih[2], il[2], jh, jl;
    auto loadG = [&](int k0) {
        #pragma unroll
        for (int i = 0; i < 2; i++) {
            int l = t + i * 256;
            int row = l >> 2, c8 = (l & 3) * 8;
            ih[i] = *(const uint4*)&g_zhi[(size_t)(bi + row) * H2d + k0 + c8];
            il[i] = *(const uint4*)&g_zlo[(size_t)(bi + row) * H2d + k0 + c8];
        }
        int row = t >> 2, c8 = (t & 3) * 8;
        jh = *(const uint4*)&g_zhi[(size_t)(bj + row) * H2d + k0 + c8];
        jl = *(const uint4*)&g_zlo[(size_t)(bj + row) * H2d + k0 + c8];
    };
    auto storeS = [&](int buf) {
        #pragma unroll
        for (int i = 0; i < 2; i++) {
            int l = t + i * 256;
            int row = l >> 2, c8 = (l & 3) * 8;
            *(uint4*)&Zih[buf][row][c8] = ih[i];
            *(uint4*)&Zil[buf][row][c8] = il[i];
        }
        int row = t >> 2, c8 = (t & 3) * 8;
        *(uint4*)&Zjh[buf][row][c8] = jh;
        *(uint4*)&Zjl[buf][row][c8] = jl;
    };

    unsigned ah[2][2][4], al[2][2][4], bh[2][4][2], bl[2][4][2];
    auto loadFrag = [&](int c_, int ks, int slot) {
        #pragma unroll
        for (int tn = 0; tn < 2; tn++) {
            int row = wy * 32 + tn * 16 + (lane & 15);
            int kof = ks + ((lane >> 4) << 3);
            ldsm4(ah[slot][tn], sptr(&Zih[c_][row][kof]));
            ldsm4(al[slot][tn], sptr(&Zil[c_][row][kof]));
        }
        #pragma unroll
        for (int g = 0; g < 2; g++) {
            int row = wx * 32 + g * 16 + ((lane >> 4) << 3) + (lane & 7);
            int kof = ks + (((lane >> 3) & 1) << 3);
            unsigned r[4];
            ldsm4(r, sptr(&Zjh[c_][row][kof]));
            bh[slot][2*g][0] = r[0]; bh[slot][2*g][1] = r[1];
            bh[slot][2*g+1][0] = r[2]; bh[slot][2*g+1][1] = r[3];
            ldsm4(r, sptr(&Zjl[c_][row][kof]));
            bl[slot][2*g][0] = r[0]; bl[slot][2*g][1] = r[1];
            bl[slot][2*g+1][0] = r[2]; bl[slot][2*g+1][1] = r[3];
        }
    };

    float acc[2][4][4] = {};
    auto mmaAll = [&](int slot) {
        #pragma unroll
        for (int tn = 0; tn < 2; tn++)
            #pragma unroll
            for (int tb = 0; tb < 4; tb++) {
                mma16816(acc[tn][tb], ah[slot][tn], bh[slot][tb]);
                mma16816(acc[tn][tb], ah[slot][tn], bl[slot][tb]);
                mma16816(acc[tn][tb], al[slot][tn], bh[slot][tb]);
            }
    };

    loadG(0); storeS(0); __syncthreads();
    loadFrag(0, 0, 0);
    int cur = 0;
    for (int k0 = 0; k0 < H2d; k0 += 32) {
        const int kn = k0 + 32;
        if (kn < H2d) loadG(kn);
        loadFrag(cur, 16, 1);
        mmaAll(0);
        if (kn < H2d) storeS(cur ^ 1);
        mmaAll(1);
        __syncthreads();
        cur ^= 1;
        if (kn < H2d) loadFrag(cur, 0, 0);
    }

    // ---- epilogue pass 1: keys + bce sums + per-thread saturated count ----
    const int gq = lane >> 2, tg = lane & 3;
    float s1 = 0.f, s2 = 0.f, ls = 0.f;
    int myCnt = 0;
    #pragma unroll
    for (int tn = 0; tn < 2; tn++)
        #pragma unroll
        for (int tb = 0; tb < 4; tb++)
            #pragma unroll
            for (int r = 0; r < 4; r++) {
                int gi = bi + wy * 32 + tn * 16 + gq + ((r >> 1) << 3);
                int gj = bj + wx * 32 + tb * 8 + 2 * tg + (r & 1);
                float x = acc[tn][tb][r];
                bool sat = (x >= xstar);
                float texp = __expf(-x);
                float pa = __fdividef(1.f, 1.f + texp);
                float L = labels[(size_t)gi * Nn + gj];
                float tt = __expf(-pa);
                float u  = __logf(1.f + tt);
                s1 += L * (-u);
                s2 += (1.f - L) * (-(pa + u));
                ls += L;
                unsigned pb = __float_as_uint(pa);
                pb = sat ? 0x3F800000u : (pb >= 0x3F800000u ? 0x3F7FFFFFu : pb);
                bool up = (gj > gi);
                unsigned key = up ? pb : 0u;
                g_keys[(size_t)gi * Nn + gj] = key;
                myCnt += (sat && up) ? 1 : 0;
            }

    __shared__ int scnt[256];
    __shared__ int sbase;
    scnt[t] = myCnt; __syncthreads();
    #pragma unroll
    for (int off = 1; off < 256; off <<= 1) {
        int v = (t >= off) ? scnt[t - off] : 0;
        __syncthreads();
        scnt[t] += v;
        __syncthreads();
    }
    if (t == 255) sbase = atomicAdd(&g_candCount, scnt[255]);
    __syncthreads();
    int wpos = sbase + scnt[t] - myCnt;

    if (myCnt > 0) {
        #pragma unroll
        for (int tn = 0; tn < 2; tn++)
            #pragma unroll
            for (int tb = 0; tb < 4; tb++)
                #pragma unroll
                for (int r = 0; r < 4; r++) {
                    int gi = bi + wy * 32 + tn * 16 + gq + ((r >> 1) << 3);
                    int gj = bj + wx * 32 + tb * 8 + 2 * tg + (r & 1);
                    if (gj > gi && acc[tn][tb][r] >= xstar) {
                        unsigned idx = (unsigned)(gi * Nn + gj);
                        if (wpos < CAPBIG)
                            g_candBig[wpos] = (0x3F800000ull << 32)
                                            | (0xFFFFFFFFu - idx);
                        wpos++;
                    }
                }
    }

    __shared__ float red[256];
    red[t] = s1; __syncthreads();
    for (int st = 128; st > 0; st >>= 1) { if (t < st) red[t] += red[t + st]; __syncthreads(); }
    float bs1 = red[0]; __syncthreads();
    red[t] = s2; __syncthreads();
    for (int st = 128; st > 0; st >>= 1) { if (t < st) red[t] += red[t + st]; __syncthreads(); }
    float bs2 = red[0]; __syncthreads();
    red[t] = ls; __syncthreads();
    for (int st = 128; st > 0; st >>= 1) { if (t < st) red[t] += red[t + st]; __syncthreads(); }
    if (t == 0) {
        atomicAdd(&g_sums[1], (double)bs1);
        atomicAdd(&g_sums[2], (double)bs2);
        atomicAdd(&g_sums[0], (double)red[0]);
    }
}

// --- fused topk tail + select + gather + scalars ------------------------------
__global__ void __launch_bounds__(256) topkFused_k(float* __restrict__ out)
{
    const int lane = threadIdx.x & 31;
    const int stride = gridDim.x * blockDim.x;
    __shared__ unsigned Ssum[256];
    int ph = 0;
    auto gsync = [&]() {
        __syncthreads();
        if (threadIdx.x == 0) {
            __threadfence();
            atomicAdd(&g_bar, 1u);
            ph++;
            while (atomicAdd(&g_bar, 0u) < (unsigned)(ph * gridDim.x)) {}
            __threadfence();
        }
        __syncthreads();
    };

    if (blockIdx.x == 0 && threadIdx.x == 0) {
        if (g_candCount >= MAXK) {
            g_meta[0] = 0x3F80u; g_meta[1] = 0u;
            g_meta[2] = 0x3F800000u; g_meta[3] = 0u;
            g_meta[7] = 1u;
        } else {
            g_meta[7] = 0u; g_candCount = 0;
        }
    }
    gsync();
    const unsigned ok = g_meta[7];

    if (!ok) {
        for (int base = blockIdx.x * blockDim.x; base < Nn * Nn; base += stride) {
            int i = base + threadIdx.x;
            unsigned key = g_keys[i];
            unsigned m = __ballot_sync(0xffffffffu, key != 0u);
            if (key != 0u) {
                unsigned bin = key >> 16;
                unsigned peers = __match_any_sync(m, bin);
                if ((unsigned)(__ffs(peers) - 1) == (unsigned)lane)
                    atomicAdd(&g_hist1[bin], (unsigned)__popc(peers));
            }
        }
        gsync();
        if (blockIdx.x == 0) {
            const int t = threadIdx.x;
            const int base = t * 256;
            unsigned local = 0;
            for (int i = 0; i < 256; i++) local += g_hist1[base + i];
            Ssum[t] = local; __syncthreads();
            for (int off = 1; off < 256; off <<= 1) {
                unsigned v = (t + off < 256) ? Ssum[t + off] : 0u;
                __syncthreads();
                Ssum[t] += v;
                __syncthreads();
            }
            unsigned cum = Ssum[t] - local;
            for (int b = base + 255; b >= base; b--) {
                unsigned h = g_hist1[b];
                if (cum < MAXK && cum + h >= MAXK) { g_meta[0] = (unsigned)b; g_meta[1] = cum; }
                cum += h;
            }
        }
        gsync();
        {
            const unsigned P1 = g_meta[0];
            for (int base = blockIdx.x * blockDim.x; base < Nn * Nn; base += stride) {
                int i = base + threadIdx.x;
                unsigned key = g_keys[i];
                bool take = (key != 0u) && ((key >> 16) >= P1);
                unsigned m = __ballot_sync(0xffffffffu, take);
                if (m) {
                    int leader = __ffs(m) - 1;
                    int pbase = 0;
                    if (lane == leader) pbase = atomicAdd(&g_candCount, __popc(m));
                    pbase = __shfl_sync(0xffffffffu, pbase, leader);
                    if (take) {
                        int pos = pbase + __popc(m & ((1u << lane) - 1u));
                        if (pos < CAPBIG)
                            g_candBig[pos] = ((unsigned long long)key << 32)
                                           | (unsigned)(0xFFFFFFFFu - (unsigned)i);
                    }
                }
            }
        }
        gsync();
        {
            const int cnt2 = g_candCount < CAPBIG ? g_candCount : CAPBIG;
            const unsigned P1 = g_meta[0];
            for (int base = blockIdx.x * blockDim.x; base < cnt2; base += stride) {
                int i = base + threadIdx.x;
                unsigned key = 0u;
                if (i < cnt2) key = (unsigned)(g_candBig[i] >> 32);
                bool on = (i < cnt2) && ((key >> 16) == P1);
                unsigned m = __ballot_sync(0xffffffffu, on);
                if (on) {
                    unsigned bin = key & 0xFFFFu;
                    unsigned peers = __match_any_sync(m, bin);
                    if ((unsigned)(__ffs(peers) - 1) == (unsigned)lane)
                        atomicAdd(&g_hist2[bin], (unsigned)__popc(peers));
                }
            }
        }
        gsync();
        if (blockIdx.x == 0) {
            const int t = threadIdx.x;
            const int base = t * 256;
            const unsigned cA1 = g_meta[1];
            const unsigned P1 = g_meta[0];
            unsigned local = 0;
            for (int i = 0; i < 256; i++) local += g_hist2[base + i];
            Ssum[t] = local; __syncthreads();
            for (int off = 1; off < 256; off <<= 1) {
                unsigned v = (t + off < 256) ? Ssum[t + off] : 0u;
                __syncthreads();
                Ssum[t] += v;
                __syncthreads();
            }
            unsigned cum = cA1 + Ssum[t] - local;
            for (int b = base + 255; b >= base; b--) {
                unsigned h = g_hist2[b];
                if (cum < MAXK && cum + h >= MAXK) {
                    g_meta[2] = (P1 << 16) | (unsigned)b;
                    g_meta[3] = cum;
                }
                cum += h;
            }
        }
        gsync();
    }

    const int count = g_candCount < CAPBIG ? g_candCount : CAPBIG;

    {
        const unsigned TH = g_meta[2];
        for (int base = blockIdx.x * blockDim.x; base < count; base += stride) {
            int i = base + threadIdx.x;
            unsigned long long c = 0ull;
            if (i < count) c = g_candBig[i];
            bool on = (i < count) && ((unsigned)(c >> 32) == TH);
            unsigned m = __ballot_sync(0xffffffffu, on);
            if (on) {
                unsigned bin = ((unsigned)c) >> 16;
                unsigned peers = __match_any_sync(m, bin);
                if ((unsigned)(__ffs(peers) - 1) == (unsigned)lane)
                    atomicAdd(&g_hist3[bin], (unsigned)__popc(peers));
            }
        }
    }
    gsync();
    if (blockIdx.x == 0) {
        const int t = threadIdx.x;
        const int base = t * 256;
        const unsigned need = MAXK - g_meta[3];
        unsigned local = 0;
        for (int i = 0; i < 256; i++) local += g_hist3[base + i];
        Ssum[t] = local; __syncthreads();
        for (int off = 1; off < 256; off <<= 1) {
            unsigned v = (t + off < 256) ? Ssum[t + off] : 0u;
            __syncthreads();
            Ssum[t] += v;
            __syncthreads();
        }
        unsigned cum = Ssum[t] - local;
        for (int b = base + 255; b >= base; b--) {
            unsigned h = g_hist3[b];
            if (cum < need && cum + h >= need) { g_meta[4] = (unsigned)b; g_meta[5] = cum; }
            cum += h;
        }
    }
    gsync();
    {
        const unsigned TH = g_meta[2];
        const unsigned S1 = g_meta[4];
        for (int base = blockIdx.x * blockDim.x; base < count; base += stride) {
            int i = base + threadIdx.x;
            unsigned long long c = 0ull;
            if (i < count) c = g_candBig[i];
            unsigned sec = (unsigned)c;
            bool on = (i < count) && ((unsigned)(c >> 32) == TH) && ((sec >> 16) == S1);
            unsigned m = __ballot_sync(0xffffffffu, on);
            if (on) {
                unsigned bin = sec & 0xFFFFu;
                unsigned peers = __match_any_sync(m, bin);
                if ((unsigned)(__ffs(peers) - 1) == (unsigned)lane)
                    atomicAdd(&g_hist4[bin], (unsigned)__popc(peers));
            }
        }
    }
    gsync();
    if (blockIdx.x == 0) {
        const int t = threadIdx.x;
        const int base = t * 256;
        const unsigned need = MAXK - g_meta[3];
        const unsigned cA = g_meta[5];
        const unsigned S1 = g_meta[4];
        unsigned local = 0;
        for (int i = 0; i < 256; i++) local += g_hist4[base + i];
        Ssum[t] = local; __syncthreads();
        for (int off = 1; off < 256; off <<= 1) {
            unsigned v = (t + off < 256) ? Ssum[t + off] : 0u;
            __syncthreads();
            Ssum[t] += v;
            __syncthreads();
        }
        unsigned cum = cA + Ssum[t] - local;
        for (int b = base + 255; b >= base; b--) {
            unsigned h = g_hist4[b];
            if (cum < need && cum + h >= need) g_meta[6] = (S1 << 16) | (unsigned)b;
            cum += h;
        }
    }
    gsync();
    {
        const unsigned TH = g_meta[2];
        const unsigned SECTH = g_meta[6];
        for (int base = blockIdx.x * blockDim.x; base < count; base += stride) {
            int i = base + threadIdx.x;
            unsigned long long c = 0ull;
            if (i < count) c = g_candBig[i];
            unsigned key = (unsigned)(c >> 32);
            unsigned sec = (unsigned)c;
            bool take = (i < count) && ((key > TH) || (key == TH && sec >= SECTH));
            unsigned m = __ballot_sync(0xffffffffu, take);
            if (m) {
                int leader = __ffs(m) - 1;
                int pbase = 0;
                if (lane == leader) pbase = atomicAdd(&g_candCount2, __popc(m));
                pbase = __shfl_sync(0xffffffffu, pbase, leader);
                if (take) {
                    int pos = pbase + __popc(m & ((1u << lane) - 1u));
                    if (pos < CAP) g_cand[pos] = c;
                }
            }
        }
    }
    gsync();
    if (blockIdx.x == 0) {
        int C = g_candCount2; if (C > CAP) C = CAP;
        const int t = threadIdx.x;
        __shared__ unsigned long long sc[CAP];
        for (int c = t; c < C; c += 256) sc[c] = g_cand[c];
        __syncthreads();
        for (int c = t; c < C; c += 256) {
            unsigned long long me = sc[c];
            int rank = 0;
            for (int o = 0; o < C; o++) rank += (sc[o] > me);
            if (rank < MAXK) {
                unsigned lo = (unsigned)(me & 0xFFFFFFFFu);
                g_sel[rank] = (int)(0xFFFFFFFFu - lo);
            }
        }
    }
    gsync();
    for (int e = blockIdx.x * blockDim.x + threadIdx.x; e < MAXK * H2d; e += stride) {
        int r = e >> 8, c = e & 255;
        int idx = g_sel[r];
        int a = idx >> 11, b = idx & 2047;
        out[e] = g_ns2[(size_t)a * H2d + c] + g_ns2[(size_t)b * H2d + c];
    }
    if (blockIdx.x == 0) {
        for (int i = threadIdx.x; i < MAXK; i += 256) out[MAXK * H2d + i] = 0.f;
        if (threadIdx.x == 0) {
            double sLab = g_sums[0], s1 = g_sums[1], s2 = g_sums[2], kls = g_sums[3];
            double n = (double)Nn, n2 = n * n;
            double pw   = (n2 - sLab + n) / (sLab - n + 0.01);
            double norm = n2 / (n2 - sLab + n);
            double recons = norm * (-(pw * s1 + s2) / n2);
            double kld = 0.5 * kls / n2;
            out[MAXK * H2d + MAXK]     = (float)recons;
            out[MAXK * H2d + MAXK + 1] = (float)kld;
        }
    }
}

// ------------------------- host launcher --------------------------------------
template <typename T>
static float* symaddr(T& sym) { void* p = nullptr; cudaGetSymbolAddress(&p, sym); return (float*)p; }

extern "C" void kernel_launch(void* const* d_in, const int* in_sizes, int n_in,
                              void* d_out, int out_size)
{
    const float* ns_emb = (const float*)d_in[0];
    const float* adj    = (const float*)d_in[1];
    const float* adjp   = (const float*)d_in[2];
    const float* cond   = (const float*)d_in[3];
    const float* labels = (const float*)d_in[4];
    const float* eps    = (const float*)d_in[5];
    const float* W_map  = (const float*)d_in[6];
    const float* W[14];
    for (int i = 0; i < 14; i++) W[i] = (const float*)d_in[7 + i];
    float* out = (float*)d_out;

    float* Sb   = symaddr(g_S);
    float* Hidb = symaddr(g_Hid);
    float* Qb   = symaddr(g_Q);
    float* Kbb  = symaddr(g_Kb);
    float* Vbb  = symaddr(g_Vb);
    float* attb = symaddr(g_att);
    float* Ob   = symaddr(g_O);
    float* Mhb  = symaddr(g_Mh);
    float* Tb   = symaddr(g_T);
    float* mu   = symaddr(g_mu);
    float* lv   = symaddr(g_lv);
    float* mupr = symaddr(g_mupr);
    float* lvpr = symaddr(g_lvpr);
    float* ns2  = symaddr(g_ns2);

    auto S   = [&](int e){ return Sb   + (size_t)e * Nn  * H1d; };
    auto Hid = [&](int e){ return Hidb + (size_t)e * Nn  * H1d; };
    auto Q   = [&](int e){ return Qb   + (size_t)e * Nn  * H1d; };
    auto Kb  = [&](int e){ return Kbb  + (size_t)e * LCd * H1d; };
    auto Vb  = [&](int e){ return Vbb  + (size_t)e * LCd * H1d; };
    auto ATT = [&](int b){ return attb + (size_t)b * Nn  * LCd; };
    auto O   = [&](int e){ return Ob   + (size_t)e * Nn  * H1d; };
    auto Mh  = [&](int e){ return Mhb  + (size_t)e * Nn  * H1d; };
    auto T   = [&](int b){ return Tb   + (size_t)b * Nn  * H2d; };

    auto gemm = [&](GPtrs p, int bat, int M, int N, int K,
                    int lda, int ldb, int ldc, float alpha, int transB, int act) {
        dim3 grd(N / 64, M / 128, bat);
        if (transB) gemmT_k<1><<<grd, 256>>>(p, K, lda, ldb, ldc, alpha, act);
        else        gemmT_k<0><<<grd, 256>>>(p, K, lda, ldb, ldc, alpha, act);
    };

    csrB_k<<<dim3(Nn / 8, 2), 256>>>(adj, adjp);

    // S[e] = leaky(ns_emb @ W_hid[e])
    { GPtrs p = {{ns_emb, ns_emb}, {W[0], W[7]}, {S(0), S(1)}};
      gemm(p, 2, Nn, H1d, FIN, FIN, H1d, H1d, 1.f, 0, 1); }
    // Hid[e] = adj[e] (sparse) @ S[e]
    { SpArgs a = {{S(0), S(1)}, {Hid(0), Hid(1)}, {0, 1}};
      spmmB_k<<<dim3(Nn, 2), H1d / 4>>>(a, H1d); }
    // Q[e] = Hid[e] @ Wq[e]
    { GPtrs p = {{Hid(0), Hid(1)}, {W[1], W[8]}, {Q(0), Q(1)}};
      gemm(p, 2, Nn, H1d, H1d, H1d, H1d, H1d, 1.f, 0, 0); }
    // K/V for both encoders (M=256)
    { GPtrs p = {{cond, cond, cond, cond}, {W[2], W[3], W[9], W[10]},
                 {Kb(0), Vb(0), Kb(1), Vb(1)}};
      gemm(p, 4, LCd, H1d, FIN, FIN, H1d, H1d, 1.f, 0, 0); }
    // att[b=(e,h)] = Q[e]_h @ Kb[e]_h^T / 16
    { GPtrs p = {{Q(0), Q(0) + 256, Q(1), Q(1) + 256},
                 {Kb(0), Kb(0) + 256, Kb(1), Kb(1) + 256},
                 {ATT(0), ATT(1), ATT(2), ATT(3)}};
      gemm(p, 4, Nn, LCd, 256, H1d, H1d, LCd, 1.f / 16.f, 1, 0); }
    softmax_k<<<4 * Nn, 256>>>(attb);
    // O[e]_h = att[b] @ Vb[e]_h
    { GPtrs p = {{ATT(0), ATT(1), ATT(2), ATT(3)},
                 {Vb(0), Vb(0) + 256, Vb(1), Vb(1) + 256},
                 {O(0), O(0) + 256, O(1), O(1) + 256}};
      gemm(p, 4, Nn, 256, LCd, LCd, H1d, H1d, 1.f, 0, 0); }
    // Mh[e] = O[e] @ Wo[e]
    { GPtrs p = {{O(0), O(1)}, {W[4], W[11]}, {Mh(0), Mh(1)}};
      gemm(p, 2, Nn, H1d, H1d, H1d, H1d, H1d, 1.f, 0, 0); }
    // T[0..3] = leaky(Mh[e] @ {Wmu[e], Wvar[e]})
    { GPtrs p = {{Mh(0), Mh(0), Mh(1), Mh(1)}, {W[5], W[6], W[12], W[13]},
                 {T(0), T(1), T(2), T(3)}};
      gemm(p, 4, Nn, H2d, H1d, H1d, H2d, H2d, 1.f, 0, 1); }
    // {mu, lv, mupr, lvpr} = adj[e] (sparse) @ T[b]
    { SpArgs a = {{T(0), T(1), T(2), T(3)}, {mu, lv, mupr, lvpr}, {0, 0, 1, 1}};
      spmmB_k<<<dim3(Nn, 4), H2d / 4>>>(a, H2d); }

    zkld_k<<<Nn * H2d / 256, 256>>>(eps);
    gemmNS_k<<<dim3(H2d / 64, Nn / 128), 256>>>(ns_emb, W_map, ns2, FIN, FIN, H2d, H2d);

    decoder_k<<<dim3(Nn / 64, Nn / 128), 256>>>(labels);
    topkFused_k<<<NBLK, 256>>>(out);

    (void)in_sizes; (void)n_in; (void)out_size;
}

// round 16
// speedup vs baseline: 1.0244x; 1.0244x over previous
#include <cuda_runtime.h>
#include <cuda_bf16.h>
#include <math.h>

#define Nn   2048
#define FIN  768
#define H1d  512
#define H2d  256
#define LCd  256
#define MAXK 512
#define CAP  1024
#define ELLW 64
#define CAPBIG 2100000
#define NBLK 148

// ------------------------- device scratch (no allocs allowed) ---------------
__device__ float g_S  [2*Nn*H1d];
__device__ float g_Hid[2*Nn*H1d];
__device__ float g_Q  [2*Nn*H1d];
__device__ float g_Kb [2*LCd*H1d];
__device__ float g_Vb [2*LCd*H1d];
__device__ float g_att[4*Nn*LCd];
__device__ float g_O  [2*Nn*H1d];
__device__ float g_Mh [2*Nn*H1d];
__device__ float g_T  [4*Nn*H2d];
__device__ float g_mu  [Nn*H2d];
__device__ float g_lv  [Nn*H2d];
__device__ float g_mupr[Nn*H2d];
__device__ float g_lvpr[Nn*H2d];
__device__ unsigned short g_zhi[Nn*H2d];
__device__ unsigned short g_zlo[Nn*H2d];
__device__ float g_ns2[Nn*H2d];
__device__ unsigned g_keys[(size_t)Nn*Nn];
__device__ unsigned g_hist1[65536];
__device__ unsigned g_hist2[65536];
__device__ unsigned g_hist3[65536];
__device__ unsigned g_hist4[65536];
__device__ double   g_sums[4];
__device__ unsigned g_meta[8];
__device__ unsigned g_xstar;
__device__ unsigned g_bar;
__device__ int      g_candCount;
__device__ int      g_candCount2;
__device__ unsigned long long g_candBig[CAPBIG];
__device__ unsigned long long g_cand[CAP];
__device__ int      g_sel[MAXK];
__device__ int   g_nnz [2][Nn];
__device__ int   g_cols[2][Nn*ELLW];
__device__ float g_vals[2][Nn*ELLW];

__device__ __forceinline__ float leakyf(float x) { return x >= 0.f ? x : 0.01f * x; }

struct GPtrs  { const float* A[4]; const float* B[4]; float* C[4]; };
struct SpArgs { const float* X[4]; float* Y[4]; int wh[4]; };

// ------------------------- mma helpers ---------------------------------------
__device__ __forceinline__ unsigned sptr(const void* p) {
    return (unsigned)__cvta_generic_to_shared(p);
}
__device__ __forceinline__ void ldsm4(unsigned* r, unsigned addr) {
    asm volatile("ldmatrix.sync.aligned.m8n8.x4.shared.b16 {%0,%1,%2,%3},[%4];"
                 : "=r"(r[0]), "=r"(r[1]), "=r"(r[2]), "=r"(r[3]) : "r"(addr));
}
__device__ __forceinline__ void ldsm4t(unsigned* r, unsigned addr) {
    asm volatile("ldmatrix.sync.aligned.m8n8.x4.trans.shared.b16 {%0,%1,%2,%3},[%4];"
                 : "=r"(r[0]), "=r"(r[1]), "=r"(r[2]), "=r"(r[3]) : "r"(addr));
}
__device__ __forceinline__ void mma16816(float* c, const unsigned* a, const unsigned* b) {
    asm volatile("mma.sync.aligned.m16n8k16.row.col.f32.bf16.bf16.f32 "
                 "{%0,%1,%2,%3},{%4,%5,%6,%7},{%8,%9},{%0,%1,%2,%3};"
                 : "+f"(c[0]), "+f"(c[1]), "+f"(c[2]), "+f"(c[3])
                 : "r"(a[0]), "r"(a[1]), "r"(a[2]), "r"(a[3]), "r"(b[0]), "r"(b[1]));
}
__device__ __forceinline__ uint2 cvtf4(float4 v) {
    __nv_bfloat162 lo = __float22bfloat162_rn(make_float2(v.x, v.y));
    __nv_bfloat162 hi = __float22bfloat162_rn(make_float2(v.z, v.w));
    uint2 u; u.x = *(unsigned*)&lo; u.y = *(unsigned*)&hi; return u;
}
__device__ __forceinline__ void splitf4(float4 v, uint2& H, uint2& L) {
    __nv_bfloat16 h0 = __float2bfloat16(v.x), h1 = __float2bfloat16(v.y);
    __nv_bfloat16 h2 = __float2bfloat16(v.z), h3 = __float2bfloat16(v.w);
    __nv_bfloat16 l0 = __float2bfloat16(v.x - __bfloat162float(h0));
    __nv_bfloat16 l1 = __float2bfloat16(v.y - __bfloat162float(h1));
    __nv_bfloat16 l2 = __float2bfloat16(v.z - __bfloat162float(h2));
    __nv_bfloat16 l3 = __float2bfloat16(v.w - __bfloat162float(h3));
    H.x = (unsigned)*(unsigned short*)&h0 | ((unsigned)*(unsigned short*)&h1 << 16);
    H.y = (unsigned)*(unsigned short*)&h2 | ((unsigned)*(unsigned short*)&h3 << 16);
    L.x = (unsigned)*(unsigned short*)&l0 | ((unsigned)*(unsigned short*)&l1 << 16);
    L.y = (unsigned)*(unsigned short*)&l2 | ((unsigned)*(unsigned short*)&l3 << 16);
}

// -- batched bf16 tensor-core GEMM, 128x64 tile, frag-pipelined, overlay epi --
template<int TRANSB>
__global__ void __launch_bounds__(256) gemmT_k(GPtrs p, int K, int lda, int ldb, int ldc,
                                               float alpha, int act)
{
    constexpr int BR = TRANSB ? 64 : 32;
    constexpr int BC = TRANSB ? 40 : 72;
    constexpr int AS_B = 2 * 128 * 40 * 2;
    constexpr int BS_B = 2 * BR * BC * 2;
    constexpr int CS_B = 128 * 68 * 4;
    constexpr int SM_B = (AS_B + BS_B > CS_B) ? (AS_B + BS_B) : CS_B;
    __shared__ __align__(16) char smraw[SM_B];
    typedef unsigned short ArrA[128][40];
    typedef unsigned short ArrB[BR][BC];
    ArrA* As = reinterpret_cast<ArrA*>(smraw);
    ArrB* Bs = reinterpret_cast<ArrB*>(smraw + AS_B);
    float (*Cs)[68] = reinterpret_cast<float(*)[68]>(smraw);

    const float* __restrict__ A = p.A[blockIdx.z];
    const float* __restrict__ B = p.B[blockIdx.z];
    float* __restrict__ C = p.C[blockIdx.z];
    const int bm = blockIdx.y * 128, bn = blockIdx.x * 64;
    const int t = threadIdx.x, lane = t & 31, wid = t >> 5;
    const int wy = TRANSB ? (wid >> 1) : (wid & 1);
    const int wx = TRANSB ? (wid & 1)  : (wid >> 1);

    float4 aR[4], bR[2];
    auto loadG = [&](int k0) {
        #pragma unroll
        for (int i = 0; i < 4; i++) {
            int l = t + i * 256;
            aR[i] = *(const float4*)&A[(size_t)(bm + (l >> 3)) * lda + k0 + (l & 7) * 4];
        }
        #pragma unroll
        for (int i = 0; i < 2; i++) {
            int l = t + i * 256;
            if (TRANSB)
                bR[i] = *(const float4*)&B[(size_t)(bn + (l >> 3)) * ldb + k0 + (l & 7) * 4];
            else
                bR[i] = *(const float4*)&B[(size_t)(k0 + (l >> 4)) * ldb + bn + (l & 15) * 4];
        }
    };
    auto storeS = [&](int buf) {
        #pragma unroll
        for (int i = 0; i < 4; i++) {
            int l = t + i * 256;
            *(uint2*)&As[buf][l >> 3][(l & 7) * 4] = cvtf4(aR[i]);
        }
        #pragma unroll
        for (int i = 0; i < 2; i++) {
            int l = t + i * 256;
            if (TRANSB) *(uint2*)&Bs[buf][l >> 3][(l & 7) * 4] = cvtf4(bR[i]);
            else        *(uint2*)&Bs[buf][l >> 4][(l & 15) * 4] = cvtf4(bR[i]);
        }
    };

    unsigned afr[2][2][4], bfr[2][4][2];
    auto loadFrag = [&](int c_, int ks, int slot) {
        if (TRANSB) {
            #pragma unroll
            for (int tn = 0; tn < 2; tn++) {
                int row = wy * 32 + tn * 16 + (lane & 15);
                int kof = ks + ((lane >> 4) << 3);
                ldsm4(afr[slot][tn], sptr(&As[c_][row][kof]));
            }
            #pragma unroll
            for (int g = 0; g < 2; g++) {
                int row = wx * 32 + g * 16 + ((lane >> 4) << 3) + (lane & 7);
                int kof = ks + (((lane >> 3) & 1) << 3);
                unsigned r[4];
                ldsm4(r, sptr(&Bs[c_][row][kof]));
                bfr[slot][2*g][0] = r[0]; bfr[slot][2*g][1] = r[1];
                bfr[slot][2*g+1][0] = r[2]; bfr[slot][2*g+1][1] = r[3];
            }
        } else {
            #pragma unroll
            for (int tn = 0; tn < 2; tn++) {   // opA = B^T via trans LDSM
                int krow = ks + ((lane >> 4) << 3) + (lane & 7);
                int nof  = wy * 32 + tn * 16 + (((lane >> 3) & 1) << 3);
                ldsm4t(afr[slot][tn], sptr(&Bs[c_][krow][nof]));
            }
            #pragma unroll
            for (int g = 0; g < 2; g++) {      // opB = A^T via non-trans LDSM
                int row = wx * 32 + g * 16 + ((lane >> 4) << 3) + (lane & 7);
                int kof = ks + (((lane >> 3) & 1) << 3);
                unsigned r[4];
                ldsm4(r, sptr(&As[c_][row][kof]));
                bfr[slot][2*g][0] = r[0]; bfr[slot][2*g][1] = r[1];
                bfr[slot][2*g+1][0] = r[2]; bfr[slot][2*g+1][1] = r[3];
            }
        }
    };

    float acc[2][4][4] = {};
    auto mmaAll = [&](int slot) {
        #pragma unroll
        for (int tn = 0; tn < 2; tn++)
            #pragma unroll
            for (int tb = 0; tb < 4; tb++)
                mma16816(acc[tn][tb], afr[slot][tn], bfr[slot][tb]);
    };

    loadG(0); storeS(0); __syncthreads();
    loadFrag(0, 0, 0);
    int cur = 0;
    for (int k0 = 0; k0 < K; k0 += 32) {
        const int kn = k0 + 32;
        if (kn < K) loadG(kn);
        loadFrag(cur, 16, 1);
        mmaAll(0);
        if (kn < K) storeS(cur ^ 1);
        mmaAll(1);
        __syncthreads();
        cur ^= 1;
        if (kn < K) loadFrag(cur, 0, 0);
    }

    const int g = lane >> 2, tg = lane & 3;
    #pragma unroll
    for (int tn = 0; tn < 2; tn++)
        #pragma unroll
        for (int tb = 0; tb < 4; tb++)
            #pragma unroll
            for (int r = 0; r < 4; r++) {
                int rr = wy * 32 + tn * 16 + g + ((r >> 1) << 3);
                int cc = wx * 32 + tb * 8 + 2 * tg + (r & 1);
                if (TRANSB) Cs[rr][cc] = acc[tn][tb][r];
                else        Cs[cc][rr] = acc[tn][tb][r];
            }
    __syncthreads();
    #pragma unroll
    for (int i = 0; i < 8; i++) {
        int l = t + i * 256;
        int row = l >> 4, nq = (l & 15) * 4;
        float4 v;
        float* pv = &v.x;
        #pragma unroll
        for (int j = 0; j < 4; j++) {
            float w = Cs[row][nq + j] * alpha;
            if (act) w = leakyf(w);
            pv[j] = w;
        }
        *(float4*)&C[(size_t)(bm + row) * ldc + bn + nq] = v;
    }
}

// ---- ns2 GEMM: full-split bf16 (A=hi+lo, B=hi+lo, 3 mma) -> ~1e-5 rel error -
__global__ void __launch_bounds__(256) gemmNS_k(const float* __restrict__ A,
                                                const float* __restrict__ B,
                                                float* __restrict__ C,
                                                int K, int lda, int ldb, int ldc)
{
    constexpr int AH_B = 2 * 128 * 40 * 2;
    constexpr int BH_B = 2 * 32 * 72 * 2;
    __shared__ __align__(16) char smraw[2 * AH_B + 2 * BH_B];
    typedef unsigned short ArrA[128][40];
    typedef unsigned short ArrB[32][72];
    ArrA* Ah = reinterpret_cast<ArrA*>(smraw);
    ArrA* Al = reinterpret_cast<ArrA*>(smraw + AH_B);
    ArrB* Bh = reinterpret_cast<ArrB*>(smraw + 2 * AH_B);
    ArrB* Bl = reinterpret_cast<ArrB*>(smraw + 2 * AH_B + BH_B);
    float (*Cs)[68] = reinterpret_cast<float(*)[68]>(smraw);

    const int bm = blockIdx.y * 128, bn = blockIdx.x * 64;
    const int t = threadIdx.x, lane = t & 31, wid = t >> 5;
    const int wy = wid & 1, wx = wid >> 1;

    float4 aR[4], bR[2];
    auto loadG = [&](int k0) {
        #pragma unroll
        for (int i = 0; i < 4; i++) {
            int l = t + i * 256;
            aR[i] = *(const float4*)&A[(size_t)(bm + (l >> 3)) * lda + k0 + (l & 7) * 4];
        }
        #pragma unroll
        for (int i = 0; i < 2; i++) {
            int l = t + i * 256;
            bR[i] = *(const float4*)&B[(size_t)(k0 + (l >> 4)) * ldb + bn + (l & 15) * 4];
        }
    };
    auto storeS = [&](int buf) {
        #pragma unroll
        for (int i = 0; i < 4; i++) {
            int l = t + i * 256;
            uint2 H, L; splitf4(aR[i], H, L);
            *(uint2*)&Ah[buf][l >> 3][(l & 7) * 4] = H;
            *(uint2*)&Al[buf][l >> 3][(l & 7) * 4] = L;
        }
        #pragma unroll
        for (int i = 0; i < 2; i++) {
            int l = t + i * 256;
            uint2 H, L; splitf4(bR[i], H, L);
            *(uint2*)&Bh[buf][l >> 4][(l & 15) * 4] = H;
            *(uint2*)&Bl[buf][l >> 4][(l & 15) * 4] = L;
        }
    };

    loadG(0); storeS(0); __syncthreads();

    float acc[2][4][4] = {};
    int cur = 0;
    for (int k0 = 0; k0 < K; k0 += 32) {
        const int kn = k0 + 32;
        if (kn < K) loadG(kn);
        #pragma unroll
        for (int ks = 0; ks < 32; ks += 16) {
            unsigned ah[2][4], al[2][4], bh[4][2], bl[4][2];
            #pragma unroll
            for (int tn = 0; tn < 2; tn++) {
                int krow = ks + ((lane >> 4) << 3) + (lane & 7);
                int nof  = wy * 32 + tn * 16 + (((lane >> 3) & 1) << 3);
                ldsm4t(ah[tn], sptr(&Bh[cur][krow][nof]));
                ldsm4t(al[tn], sptr(&Bl[cur][krow][nof]));
            }
            #pragma unroll
            for (int g = 0; g < 2; g++) {
                int row = wx * 32 + g * 16 + ((lane >> 4) << 3) + (lane & 7);
                int kof = ks + (((lane >> 3) & 1) << 3);
                unsigned r[4];
                ldsm4(r, sptr(&Ah[cur][row][kof]));
                bh[2*g][0] = r[0]; bh[2*g][1] = r[1];
                bh[2*g+1][0] = r[2]; bh[2*g+1][1] = r[3];
                ldsm4(r, sptr(&Al[cur][row][kof]));
                bl[2*g][0] = r[0]; bl[2*g][1] = r[1];
                bl[2*g+1][0] = r[2]; bl[2*g+1][1] = r[3];
            }
            #pragma unroll
            for (int tn = 0; tn < 2; tn++)
                #pragma unroll
                for (int tb = 0; tb < 4; tb++) {
                    mma16816(acc[tn][tb], ah[tn], bh[tb]);
                    mma16816(acc[tn][tb], ah[tn], bl[tb]);
                    mma16816(acc[tn][tb], al[tn], bh[tb]);
                }
        }
        if (kn < K) storeS(cur ^ 1);
        __syncthreads();
        cur ^= 1;
    }

    const int g = lane >> 2, tg = lane & 3;
    #pragma unroll
    for (int tn = 0; tn < 2; tn++)
        #pragma unroll
        for (int tb = 0; tb < 4; tb++)
            #pragma unroll
            for (int r = 0; r < 4; r++) {
                int rr = wy * 32 + tn * 16 + g + ((r >> 1) << 3);
                int cc = wx * 32 + tb * 8 + 2 * tg + (r & 1);
                Cs[cc][rr] = acc[tn][tb][r];
            }
    __syncthreads();
    #pragma unroll
    for (int i = 0; i < 8; i++) {
        int l = t + i * 256;
        int row = l >> 4, nq = (l & 15) * 4;
        float4 v;
        float* pv = &v.x;
        #pragma unroll
        for (int j = 0; j < 4; j++)
            pv[j] = leakyf(Cs[row][nq + j]);
        *(float4*)&C[(size_t)(bm + row) * ldc + bn + nq] = v;
    }
}

// ----- ELL build (warp per row) + absorbed scratch zeroing + x* search -------
__global__ void csrB_k(const float* __restrict__ a0, const float* __restrict__ a1)
{
    const int lb = blockIdx.y * gridDim.x + blockIdx.x;   // 0..511
    {
        int i = lb * 128 + (threadIdx.x & 127);
        if (threadIdx.x < 128) { g_hist1[i] = 0; g_hist2[i] = 0; }
        else                   { g_hist3[i] = 0; g_hist4[i] = 0; }
    }
    if (lb == 0) {
        if (threadIdx.x < 4) g_sums[threadIdx.x] = 0.0;
        if (threadIdx.x >= 4 && threadIdx.x < 12) g_meta[threadIdx.x - 4] = 0u;
        if (threadIdx.x == 12) { g_candCount = 0; g_candCount2 = 0; g_bar = 0u; }
        if (threadIdx.x == 13) {
            unsigned lo = __float_as_uint(8.0f), hi = __float_as_uint(24.0f);
            while (lo < hi) {
                unsigned mid = lo + (hi - lo) / 2;
                float x = __uint_as_float(mid);
                float p = 1.f / (1.f + expf(-x));
                if (p == 1.0f) hi = mid; else lo = mid + 1;
            }
            g_xstar = lo;
        }
    }

    const int which = blockIdx.y;
    const float* adjM = which ? a1 : a0;
    int row  = blockIdx.x * (blockDim.x >> 5) + (threadIdx.x >> 5);
    int lane = threadIdx.x & 31;
    if (row >= Nn) return;
    const float* r = adjM + (size_t)row * Nn;
    int cnt = 0;
    for (int c0 = 0; c0 < Nn; c0 += 32) {
        float v = r[c0 + lane];
        unsigned m = __ballot_sync(0xffffffffu, v != 0.f);
        if (v != 0.f) {
            int pos = cnt + __popc(m & ((1u << lane) - 1u));
            if (pos < ELLW) {
                g_cols[which][row * ELLW + pos] = c0 + lane;
                g_vals[which][row * ELLW + pos] = v;
            }
        }
        cnt += __popc(m);
    }
    if (lane == 0) g_nnz[which][row] = cnt > ELLW ? ELLW : cnt;
}

// ----------- batched SpMM: Y[row, :] = leaky(sum a_rj X[j, :]), float4 -------
__global__ void spmmB_k(SpArgs a, int C)
{
    const int b   = blockIdx.y;
    const int row = blockIdx.x;
    const int which = a.wh[b];
    const float* __restrict__ X = a.X[b];
    float* __restrict__ Y = a.Y[b];
    __shared__ int   soff[ELLW];
    __shared__ float sv[ELLW];
    const int cnt = g_nnz[which][row];
    const int t = threadIdx.x;
    if (t < ELLW && t < cnt) {
        soff[t] = g_cols[which][row * ELLW + t] * C;
        sv[t]   = g_vals[which][row * ELLW + t];
    }
    __syncthreads();
    const int c = t * 4;
    float4 acc = {0.f, 0.f, 0.f, 0.f};
    #pragma unroll 8
    for (int k = 0; k < cnt; k++) {
        float4 xv = *(const float4*)&X[soff[k] + c];
        float s = sv[k];
        acc.x += s * xv.x; acc.y += s * xv.y;
        acc.z += s * xv.z; acc.w += s * xv.w;
    }
    float4 o = {leakyf(acc.x), leakyf(acc.y), leakyf(acc.z), leakyf(acc.w)};
    *(float4*)&Y[(size_t)row * C + c] = o;
}

// ------------------------- softmax over rows of 256 --------------------------
__global__ void softmax_k(float* __restrict__ s)
{
    const int row = blockIdx.x;
    float* p = s + (size_t)row * 256;
    const int t = threadIdx.x;
    __shared__ float red[256];
    float v = p[t];
    red[t] = v; __syncthreads();
    for (int st = 128; st > 0; st >>= 1) { if (t < st) red[t] = fmaxf(red[t], red[t + st]); __syncthreads(); }
    float mx = red[0]; __syncthreads();
    float e = expf(v - mx);
    red[t] = e; __syncthreads();
    for (int st = 128; st > 0; st >>= 1) { if (t < st) red[t] += red[t + st]; __syncthreads(); }
    p[t] = e / red[0];
}

// --- fused: z = eps*exp(0.5*lv)+mu (split to bf16 hi/lo) AND KLD reduction ---
__global__ void zkld_k(const float* __restrict__ eps)
{
    const int i = blockIdx.x * blockDim.x + threadIdx.x;
    float mupo = g_mu[i], lvpo = g_lv[i];
    float zv = eps[i] * expf(0.5f * lvpo) + mupo;
    __nv_bfloat16 h = __float2bfloat16(zv);
    __nv_bfloat16 l = __float2bfloat16(zv - __bfloat162float(h));
    g_zhi[i] = *(unsigned short*)&h;
    g_zlo[i] = *(unsigned short*)&l;
    float mupr = g_mupr[i], lvpr = g_lvpr[i];
    float d = mupr - mupo;
    float term = d * d * expf(-lvpr) + expf(lvpo - lvpr) - 1.f - (lvpo - lvpr);
    __shared__ float red[256];
    const int t = threadIdx.x;
    red[t] = term; __syncthreads();
    for (int st = 128; st > 0; st >>= 1) { if (t < st) red[t] += red[t + st]; __syncthreads(); }
    if (t == 0) atomicAdd(&g_sums[3], (double)red[0]);
}

// --- decoder: x = z z^T via split-bf16 tensor cores (non-pipelined frags) ----
__global__ void __launch_bounds__(256) decoder_k(const float* __restrict__ labels)
{
    __shared__ unsigned short Zih[2][128][40];
    __shared__ unsigned short Zil[2][128][40];
    __shared__ unsigned short Zjh[2][64][40];
    __shared__ unsigned short Zjl[2][64][40];
    const int bi = blockIdx.y * 128, bj = blockIdx.x * 64;
    const int t = threadIdx.x, lane = t & 31, wid = t >> 5;
    const int wy = wid >> 1, wx = wid & 1;
    const float xstar = __uint_as_float(g_xstar);

    uint4 ih[2], il[2], jh, jl;
    auto loadG = [&](int k0) {
        #pragma unroll
        for (int i = 0; i < 2; i++) {
            int l = t + i * 256;
            int row = l >> 2, c8 = (l & 3) * 8;
            ih[i] = *(const uint4*)&g_zhi[(size_t)(bi + row) * H2d + k0 + c8];
            il[i] = *(const uint4*)&g_zlo[(size_t)(bi + row) * H2d + k0 + c8];
        }
        int row = t >> 2, c8 = (t & 3) * 8;
        jh = *(const uint4*)&g_zhi[(size_t)(bj + row) * H2d + k0 + c8];
        jl = *(const uint4*)&g_zlo[(size_t)(bj + row) * H2d + k0 + c8];
    };
    auto storeS = [&](int buf) {
        #pragma unroll
        for (int i = 0; i < 2; i++) {
            int l = t + i * 256;
            int row = l >> 2, c8 = (l & 3) * 8;
            *(uint4*)&Zih[buf][row][c8] = ih[i];
            *(uint4*)&Zil[buf][row][c8] = il[i];
        }
        int row = t >> 2, c8 = (t & 3) * 8;
        *(uint4*)&Zjh[buf][row][c8] = jh;
        *(uint4*)&Zjl[buf][row][c8] = jl;
    };

    loadG(0); storeS(0); __syncthreads();

    float acc[2][4][4] = {};
    int cur = 0;
    for (int k0 = 0; k0 < H2d; k0 += 32) {
        const int kn = k0 + 32;
        if (kn < H2d) loadG(kn);
        #pragma unroll
        for (int ks = 0; ks < 32; ks += 16) {
            unsigned ah[2][4], al[2][4], bh[4][2], bl[4][2];
            #pragma unroll
            for (int tn = 0; tn < 2; tn++) {
                int row = wy * 32 + tn * 16 + (lane & 15);
                int kof = ks + ((lane >> 4) << 3);
                ldsm4(ah[tn], sptr(&Zih[cur][row][kof]));
                ldsm4(al[tn], sptr(&Zil[cur][row][kof]));
            }
            #pragma unroll
            for (int g = 0; g < 2; g++) {
                int row = wx * 32 + g * 16 + ((lane >> 4) << 3) + (lane & 7);
                int kof = ks + (((lane >> 3) & 1) << 3);
                unsigned r[4];
                ldsm4(r, sptr(&Zjh[cur][row][kof]));
                bh[2*g][0] = r[0]; bh[2*g][1] = r[1];
                bh[2*g+1][0] = r[2]; bh[2*g+1][1] = r[3];
                ldsm4(r, sptr(&Zjl[cur][row][kof]));
                bl[2*g][0] = r[0]; bl[2*g][1] = r[1];
                bl[2*g+1][0] = r[2]; bl[2*g+1][1] = r[3];
            }
            #pragma unroll
            for (int tn = 0; tn < 2; tn++)
                #pragma unroll
                for (int tb = 0; tb < 4; tb++) {
                    mma16816(acc[tn][tb], ah[tn], bh[tb]);
                    mma16816(acc[tn][tb], ah[tn], bl[tb]);
                    mma16816(acc[tn][tb], al[tn], bh[tb]);
                }
        }
        if (kn < H2d) storeS(cur ^ 1);
        __syncthreads();
        cur ^= 1;
    }

    // ---- epilogue pass 1: keys + bce sums + per-thread saturated count ----
    const int gq = lane >> 2, tg = lane & 3;
    float s1 = 0.f, s2 = 0.f, ls = 0.f;
    int myCnt = 0;
    #pragma unroll
    for (int tn = 0; tn < 2; tn++)
        #pragma unroll
        for (int tb = 0; tb < 4; tb++)
            #pragma unroll
            for (int r = 0; r < 4; r++) {
                int gi = bi + wy * 32 + tn * 16 + gq + ((r >> 1) << 3);
                int gj = bj + wx * 32 + tb * 8 + 2 * tg + (r & 1);
                float x = acc[tn][tb][r];
                bool sat = (x >= xstar);
                float texp = __expf(-x);
                float pa = __fdividef(1.f, 1.f + texp);
                float L = labels[(size_t)gi * Nn + gj];
                float tt = __expf(-pa);
                float u  = __logf(1.f + tt);
                s1 += L * (-u);
                s2 += (1.f - L) * (-(pa + u));
                ls += L;
                unsigned pb = __float_as_uint(pa);
                pb = sat ? 0x3F800000u : (pb >= 0x3F800000u ? 0x3F7FFFFFu : pb);
                bool up = (gj > gi);
                unsigned key = up ? pb : 0u;
                g_keys[(size_t)gi * Nn + gj] = key;
                myCnt += (sat && up) ? 1 : 0;
            }

    __shared__ int scnt[256];
    __shared__ int sbase;
    scnt[t] = myCnt; __syncthreads();
    #pragma unroll
    for (int off = 1; off < 256; off <<= 1) {
        int v = (t >= off) ? scnt[t - off] : 0;
        __syncthreads();
        scnt[t] += v;
        __syncthreads();
    }
    if (t == 255) sbase = atomicAdd(&g_candCount, scnt[255]);
    __syncthreads();
    int wpos = sbase + scnt[t] - myCnt;

    if (myCnt > 0) {
        #pragma unroll
        for (int tn = 0; tn < 2; tn++)
            #pragma unroll
            for (int tb = 0; tb < 4; tb++)
                #pragma unroll
                for (int r = 0; r < 4; r++) {
                    int gi = bi + wy * 32 + tn * 16 + gq + ((r >> 1) << 3);
                    int gj = bj + wx * 32 + tb * 8 + 2 * tg + (r & 1);
                    if (gj > gi && acc[tn][tb][r] >= xstar) {
                        unsigned idx = (unsigned)(gi * Nn + gj);
                        if (wpos < CAPBIG)
                            g_candBig[wpos] = (0x3F800000ull << 32)
                                            | (0xFFFFFFFFu - idx);
                        wpos++;
                    }
                }
    }

    __shared__ float red[256];
    red[t] = s1; __syncthreads();
    for (int st = 128; st > 0; st >>= 1) { if (t < st) red[t] += red[t + st]; __syncthreads(); }
    float bs1 = red[0]; __syncthreads();
    red[t] = s2; __syncthreads();
    for (int st = 128; st > 0; st >>= 1) { if (t < st) red[t] += red[t + st]; __syncthreads(); }
    float bs2 = red[0]; __syncthreads();
    red[t] = ls; __syncthreads();
    for (int st = 128; st > 0; st >>= 1) { if (t < st) red[t] += red[t + st]; __syncthreads(); }
    if (t == 0) {
        atomicAdd(&g_sums[1], (double)bs1);
        atomicAdd(&g_sums[2], (double)bs2);
        atomicAdd(&g_sums[0], (double)red[0]);
    }
}

// --- fused topk tail + select + gather + scalars ------------------------------
__global__ void __launch_bounds__(256) topkFused_k(float* __restrict__ out)
{
    const int lane = threadIdx.x & 31;
    const int stride = gridDim.x * blockDim.x;
    __shared__ unsigned Ssum[256];
    int ph = 0;
    auto gsync = [&]() {
        __syncthreads();
        if (threadIdx.x == 0) {
            __threadfence();
            atomicAdd(&g_bar, 1u);
            ph++;
            while (atomicAdd(&g_bar, 0u) < (unsigned)(ph * gridDim.x)) {}
            __threadfence();
        }
        __syncthreads();
    };

    if (blockIdx.x == 0 && threadIdx.x == 0) {
        if (g_candCount >= MAXK) {
            g_meta[0] = 0x3F80u; g_meta[1] = 0u;
            g_meta[2] = 0x3F800000u; g_meta[3] = 0u;
            g_meta[7] = 1u;
        } else {
            g_meta[7] = 0u; g_candCount = 0;
        }
    }
    gsync();
    const unsigned ok = g_meta[7];

    if (!ok) {
        for (int base = blockIdx.x * blockDim.x; base < Nn * Nn; base += stride) {
            int i = base + threadIdx.x;
            unsigned key = g_keys[i];
            unsigned m = __ballot_sync(0xffffffffu, key != 0u);
            if (key != 0u) {
                unsigned bin = key >> 16;
                unsigned peers = __match_any_sync(m, bin);
                if ((unsigned)(__ffs(peers) - 1) == (unsigned)lane)
                    atomicAdd(&g_hist1[bin], (unsigned)__popc(peers));
            }
        }
        gsync();
        if (blockIdx.x == 0) {
            const int t = threadIdx.x;
            const int base = t * 256;
            unsigned local = 0;
            for (int i = 0; i < 256; i++) local += g_hist1[base + i];
            Ssum[t] = local; __syncthreads();
            for (int off = 1; off < 256; off <<= 1) {
                unsigned v = (t + off < 256) ? Ssum[t + off] : 0u;
                __syncthreads();
                Ssum[t] += v;
                __syncthreads();
            }
            unsigned cum = Ssum[t] - local;
            for (int b = base + 255; b >= base; b--) {
                unsigned h = g_hist1[b];
                if (cum < MAXK && cum + h >= MAXK) { g_meta[0] = (unsigned)b; g_meta[1] = cum; }
                cum += h;
            }
        }
        gsync();
        {
            const unsigned P1 = g_meta[0];
            for (int base = blockIdx.x * blockDim.x; base < Nn * Nn; base += stride) {
                int i = base + threadIdx.x;
                unsigned key = g_keys[i];
                bool take = (key != 0u) && ((key >> 16) >= P1);
                unsigned m = __ballot_sync(0xffffffffu, take);
                if (m) {
                    int leader = __ffs(m) - 1;
                    int pbase = 0;
                    if (lane == leader) pbase = atomicAdd(&g_candCount, __popc(m));
                    pbase = __shfl_sync(0xffffffffu, pbase, leader);
                    if (take) {
                        int pos = pbase + __popc(m & ((1u << lane) - 1u));
                        if (pos < CAPBIG)
                            g_candBig[pos] = ((unsigned long long)key << 32)
                                           | (unsigned)(0xFFFFFFFFu - (unsigned)i);
                    }
                }
            }
        }
        gsync();
        {
            const int cnt2 = g_candCount < CAPBIG ? g_candCount : CAPBIG;
            const unsigned P1 = g_meta[0];
            for (int base = blockIdx.x * blockDim.x; base < cnt2; base += stride) {
                int i = base + threadIdx.x;
                unsigned key = 0u;
                if (i < cnt2) key = (unsigned)(g_candBig[i] >> 32);
                bool on = (i < cnt2) && ((key >> 16) == P1);
                unsigned m = __ballot_sync(0xffffffffu, on);
                if (on) {
                    unsigned bin = key & 0xFFFFu;
                    unsigned peers = __match_any_sync(m, bin);
                    if ((unsigned)(__ffs(peers) - 1) == (unsigned)lane)
                        atomicAdd(&g_hist2[bin], (unsigned)__popc(peers));
                }
            }
        }
        gsync();
        if (blockIdx.x == 0) {
            const int t = threadIdx.x;
            const int base = t * 256;
            const unsigned cA1 = g_meta[1];
            const unsigned P1 = g_meta[0];
            unsigned local = 0;
            for (int i = 0; i < 256; i++) local += g_hist2[base + i];
            Ssum[t] = local; __syncthreads();
            for (int off = 1; off < 256; off <<= 1) {
                unsigned v = (t + off < 256) ? Ssum[t + off] : 0u;
                __syncthreads();
                Ssum[t] += v;
                __syncthreads();
            }
            unsigned cum = cA1 + Ssum[t] - local;
            for (int b = base + 255; b >= base; b--) {
                unsigned h = g_hist2[b];
                if (cum < MAXK && cum + h >= MAXK) {
                    g_meta[2] = (P1 << 16) | (unsigned)b;
                    g_meta[3] = cum;
                }
                cum += h;
            }
        }
        gsync();
    }

    const int count = g_candCount < CAPBIG ? g_candCount : CAPBIG;

    {
        const unsigned TH = g_meta[2];
        for (int base = blockIdx.x * blockDim.x; base < count; base += stride) {
            int i = base + threadIdx.x;
            unsigned long long c = 0ull;
            if (i < count) c = g_candBig[i];
            bool on = (i < count) && ((unsigned)(c >> 32) == TH);
            unsigned m = __ballot_sync(0xffffffffu, on);
            if (on) {
                unsigned bin = ((unsigned)c) >> 16;
                unsigned peers = __match_any_sync(m, bin);
                if ((unsigned)(__ffs(peers) - 1) == (unsigned)lane)
                    atomicAdd(&g_hist3[bin], (unsigned)__popc(peers));
            }
        }
    }
    gsync();
    if (blockIdx.x == 0) {
        const int t = threadIdx.x;
        const int base = t * 256;
        const unsigned need = MAXK - g_meta[3];
        unsigned local = 0;
        for (int i = 0; i < 256; i++) local += g_hist3[base + i];
        Ssum[t] = local; __syncthreads();
        for (int off = 1; off < 256; off <<= 1) {
            unsigned v = (t + off < 256) ? Ssum[t + off] : 0u;
            __syncthreads();
            Ssum[t] += v;
            __syncthreads();
        }
        unsigned cum = Ssum[t] - local;
        for (int b = base + 255; b >= base; b--) {
            unsigned h = g_hist3[b];
            if (cum < need && cum + h >= need) { g_meta[4] = (unsigned)b; g_meta[5] = cum; }
            cum += h;
        }
    }
    gsync();
    {
        const unsigned TH = g_meta[2];
        const unsigned S1 = g_meta[4];
        for (int base = blockIdx.x * blockDim.x; base < count; base += stride) {
            int i = base + threadIdx.x;
            unsigned long long c = 0ull;
            if (i < count) c = g_candBig[i];
            unsigned sec = (unsigned)c;
            bool on = (i < count) && ((unsigned)(c >> 32) == TH) && ((sec >> 16) == S1);
            unsigned m = __ballot_sync(0xffffffffu, on);
            if (on) {
                unsigned bin = sec & 0xFFFFu;
                unsigned peers = __match_any_sync(m, bin);
                if ((unsigned)(__ffs(peers) - 1) == (unsigned)lane)
                    atomicAdd(&g_hist4[bin], (unsigned)__popc(peers));
            }
        }
    }
    gsync();
    if (blockIdx.x == 0) {
        const int t = threadIdx.x;
        const int base = t * 256;
        const unsigned need = MAXK - g_meta[3];
        const unsigned cA = g_meta[5];
        const unsigned S1 = g_meta[4];
        unsigned local = 0;
        for (int i = 0; i < 256; i++) local += g_hist4[base + i];
        Ssum[t] = local; __syncthreads();
        for (int off = 1; off < 256; off <<= 1) {
            unsigned v = (t + off < 256) ? Ssum[t + off] : 0u;
            __syncthreads();
            Ssum[t] += v;
            __syncthreads();
        }
        unsigned cum = cA + Ssum[t] - local;
        for (int b = base + 255; b >= base; b--) {
            unsigned h = g_hist4[b];
            if (cum < need && cum + h >= need) g_meta[6] = (S1 << 16) | (unsigned)b;
            cum += h;
        }
    }
    gsync();
    {
        const unsigned TH = g_meta[2];
        const unsigned SECTH = g_meta[6];
        for (int base = blockIdx.x * blockDim.x; base < count; base += stride) {
            int i = base + threadIdx.x;
            unsigned long long c = 0ull;
            if (i < count) c = g_candBig[i];
            unsigned key = (unsigned)(c >> 32);
            unsigned sec = (unsigned)c;
            bool take = (i < count) && ((key > TH) || (key == TH && sec >= SECTH));
            unsigned m = __ballot_sync(0xffffffffu, take);
            if (m) {
                int leader = __ffs(m) - 1;
                int pbase = 0;
                if (lane == leader) pbase = atomicAdd(&g_candCount2, __popc(m));
                pbase = __shfl_sync(0xffffffffu, pbase, leader);
                if (take) {
                    int pos = pbase + __popc(m & ((1u << lane) - 1u));
                    if (pos < CAP) g_cand[pos] = c;
                }
            }
        }
    }
    gsync();
    if (blockIdx.x == 0) {
        int C = g_candCount2; if (C > CAP) C = CAP;
        const int t = threadIdx.x;
        __shared__ unsigned long long sc[CAP];
        for (int c = t; c < C; c += 256) sc[c] = g_cand[c];
        __syncthreads();
        for (int c = t; c < C; c += 256) {
            unsigned long long me = sc[c];
            int rank = 0;
            for (int o = 0; o < C; o++) rank += (sc[o] > me);
            if (rank < MAXK) {
                unsigned lo = (unsigned)(me & 0xFFFFFFFFu);
                g_sel[rank] = (int)(0xFFFFFFFFu - lo);
            }
        }
    }
    gsync();
    for (int e = blockIdx.x * blockDim.x + threadIdx.x; e < MAXK * H2d; e += stride) {
        int r = e >> 8, c = e & 255;
        int idx = g_sel[r];
        int a = idx >> 11, b = idx & 2047;
        out[e] = g_ns2[(size_t)a * H2d + c] + g_ns2[(size_t)b * H2d + c];
    }
    if (blockIdx.x == 0) {
        for (int i = threadIdx.x; i < MAXK; i += 256) out[MAXK * H2d + i] = 0.f;
        if (threadIdx.x == 0) {
            double sLab = g_sums[0], s1 = g_sums[1], s2 = g_sums[2], kls = g_sums[3];
            double n = (double)Nn, n2 = n * n;
            double pw   = (n2 - sLab + n) / (sLab - n + 0.01);
            double norm = n2 / (n2 - sLab + n);
            double recons = norm * (-(pw * s1 + s2) / n2);
            double kld = 0.5 * kls / n2;
            out[MAXK * H2d + MAXK]     = (float)recons;
            out[MAXK * H2d + MAXK + 1] = (float)kld;
        }
    }
}

// ------------------------- host launcher --------------------------------------
template <typename T>
static float* symaddr(T& sym) { void* p = nullptr; cudaGetSymbolAddress(&p, sym); return (float*)p; }

extern "C" void kernel_launch(void* const* d_in, const int* in_sizes, int n_in,
                              void* d_out, int out_size)
{
    const float* ns_emb = (const float*)d_in[0];
    const float* adj    = (const float*)d_in[1];
    const float* adjp   = (const float*)d_in[2];
    const float* cond   = (const float*)d_in[3];
    const float* labels = (const float*)d_in[4];
    const float* eps    = (const float*)d_in[5];
    const float* W_map  = (const float*)d_in[6];
    const float* W[14];
    for (int i = 0; i < 14; i++) W[i] = (const float*)d_in[7 + i];
    float* out = (float*)d_out;

    float* Sb   = symaddr(g_S);
    float* Hidb = symaddr(g_Hid);
    float* Qb   = symaddr(g_Q);
    float* Kbb  = symaddr(g_Kb);
    float* Vbb  = symaddr(g_Vb);
    float* attb = symaddr(g_att);
    float* Ob   = symaddr(g_O);
    float* Mhb  = symaddr(g_Mh);
    float* Tb   = symaddr(g_T);
    float* mu   = symaddr(g_mu);
    float* lv   = symaddr(g_lv);
    float* mupr = symaddr(g_mupr);
    float* lvpr = symaddr(g_lvpr);
    float* ns2  = symaddr(g_ns2);

    auto S   = [&](int e){ return Sb   + (size_t)e * Nn  * H1d; };
    auto Hid = [&](int e){ return Hidb + (size_t)e * Nn  * H1d; };
    auto Q   = [&](int e){ return Qb   + (size_t)e * Nn  * H1d; };
    auto Kb  = [&](int e){ return Kbb  + (size_t)e * LCd * H1d; };
    auto Vb  = [&](int e){ return Vbb  + (size_t)e * LCd * H1d; };
    auto ATT = [&](int b){ return attb + (size_t)b * Nn  * LCd; };
    auto O   = [&](int e){ return Ob   + (size_t)e * Nn  * H1d; };
    auto Mh  = [&](int e){ return Mhb  + (size_t)e * Nn  * H1d; };
    auto T   = [&](int b){ return Tb   + (size_t)b * Nn  * H2d; };

    auto gemm = [&](GPtrs p, int bat, int M, int N, int K,
                    int lda, int ldb, int ldc, float alpha, int transB, int act) {
        dim3 grd(N / 64, M / 128, bat);
        if (transB) gemmT_k<1><<<grd, 256>>>(p, K, lda, ldb, ldc, alpha, act);
        else        gemmT_k<0><<<grd, 256>>>(p, K, lda, ldb, ldc, alpha, act);
    };

    csrB_k<<<dim3(Nn / 8, 2), 256>>>(adj, adjp);

    // S[e] = leaky(ns_emb @ W_hid[e])
    { GPtrs p = {{ns_emb, ns_emb}, {W[0], W[7]}, {S(0), S(1)}};
      gemm(p, 2, Nn, H1d, FIN, FIN, H1d, H1d, 1.f, 0, 1); }
    // Hid[e] = adj[e] (sparse) @ S[e]
    { SpArgs a = {{S(0), S(1)}, {Hid(0), Hid(1)}, {0, 1}};
      spmmB_k<<<dim3(Nn, 2), H1d / 4>>>(a, H1d); }
    // Q[e] = Hid[e] @ Wq[e]
    { GPtrs p = {{Hid(0), Hid(1)}, {W[1], W[8]}, {Q(0), Q(1)}};
      gemm(p, 2, Nn, H1d, H1d, H1d, H1d, H1d, 1.f, 0, 0); }
    // K/V for both encoders (M=256)
    { GPtrs p = {{cond, cond, cond, cond}, {W[2], W[3], W[9], W[10]},
                 {Kb(0), Vb(0), Kb(1), Vb(1)}};
      gemm(p, 4, LCd, H1d, FIN, FIN, H1d, H1d, 1.f, 0, 0); }
    // att[b=(e,h)] = Q[e]_h @ Kb[e]_h^T / 16
    { GPtrs p = {{Q(0), Q(0) + 256, Q(1), Q(1) + 256},
                 {Kb(0), Kb(0) + 256, Kb(1), Kb(1) + 256},
                 {ATT(0), ATT(1), ATT(2), ATT(3)}};
      gemm(p, 4, Nn, LCd, 256, H1d, H1d, LCd, 1.f / 16.f, 1, 0); }
    softmax_k<<<4 * Nn, 256>>>(attb);
    // O[e]_h = att[b] @ Vb[e]_h
    { GPtrs p = {{ATT(0), ATT(1), ATT(2), ATT(3)},
                 {Vb(0), Vb(0) + 256, Vb(1), Vb(1) + 256},
                 {O(0), O(0) + 256, O(1), O(1) + 256}};
      gemm(p, 4, Nn, 256, LCd, LCd, H1d, H1d, 1.f, 0, 0); }
    // Mh[e] = O[e] @ Wo[e]
    { GPtrs p = {{O(0), O(1)}, {W[4], W[11]}, {Mh(0), Mh(1)}};
      gemm(p, 2, Nn, H1d, H1d, H1d, H1d, H1d, 1.f, 0, 0); }
    // T[0..3] = leaky(Mh[e] @ {Wmu[e], Wvar[e]})
    { GPtrs p = {{Mh(0), Mh(0), Mh(1), Mh(1)}, {W[5], W[6], W[12], W[13]},
                 {T(0), T(1), T(2), T(3)}};
      gemm(p, 4, Nn, H2d, H1d, H1d, H2d, H2d, 1.f, 0, 1); }
    // {mu, lv, mupr, lvpr} = adj[e] (sparse) @ T[b]
    { SpArgs a = {{T(0), T(1), T(2), T(3)}, {mu, lv, mupr, lvpr}, {0, 0, 1, 1}};
      spmmB_k<<<dim3(Nn, 4), H2d / 4>>>(a, H2d); }

    zkld_k<<<Nn * H2d / 256, 256>>>(eps);
    gemmNS_k<<<dim3(H2d / 64, Nn / 128), 256>>>(ns_emb, W_map, ns2, FIN, FIN, H2d, H2d);

    decoder_k<<<dim3(Nn / 64, Nn / 128), 256>>>(labels);
    topkFused_k<<<NBLK, 256>>>(out);

    (void)in_sizes; (void)n_in; (void)out_size;
}

// round 17
// speedup vs baseline: 1.0595x; 1.0342x over previous
#include <cuda_runtime.h>
#include <cuda_bf16.h>
#include <math.h>

#define Nn   2048
#define FIN  768
#define H1d  512
#define H2d  256
#define LCd  256
#define MAXK 512
#define CAP  1024
#define ELLW 64
#define CAPBIG 2100000
#define NBLK 148

// ------------------------- device scratch (no allocs allowed) ---------------
__device__ float g_S  [2*Nn*H1d];
__device__ float g_Hid[2*Nn*H1d];
__device__ float g_Q  [2*Nn*H1d];
__device__ float g_Kb [2*LCd*H1d];
__device__ float g_Vb [2*LCd*H1d];
__device__ float g_att[4*Nn*LCd];
__device__ float g_O  [2*Nn*H1d];
__device__ float g_Mh [2*Nn*H1d];
__device__ float g_T  [4*Nn*H2d];
__device__ float g_mu  [Nn*H2d];
__device__ float g_lv  [Nn*H2d];
__device__ float g_mupr[Nn*H2d];
__device__ float g_lvpr[Nn*H2d];
__device__ unsigned short g_zhi[Nn*H2d];
__device__ unsigned short g_zlo[Nn*H2d];
__device__ float g_ns2[Nn*H2d];
__device__ unsigned g_keys[(size_t)Nn*Nn];
__device__ unsigned g_hist1[65536];
__device__ unsigned g_hist2[65536];
__device__ unsigned g_hist3[65536];
__device__ unsigned g_hist4[65536];
__device__ double   g_sums[4];
__device__ unsigned g_meta[8];
__device__ unsigned g_xstar;
__device__ unsigned g_bar;
__device__ int      g_candCount;
__device__ int      g_candCount2;
__device__ unsigned long long g_candBig[CAPBIG];
__device__ unsigned long long g_cand[CAP];
__device__ int      g_sel[MAXK];
__device__ int   g_nnz [2][Nn];
__device__ int   g_cols[2][Nn*ELLW];
__device__ float g_vals[2][Nn*ELLW];

__device__ __forceinline__ float leakyf(float x) { return x >= 0.f ? x : 0.01f * x; }

struct GPtrs  { const float* A[4]; const float* B[4]; float* C[4]; };
struct SpArgs { const float* X[4]; float* Y[4]; int wh[4]; };

// ------------------------- mma helpers ---------------------------------------
__device__ __forceinline__ unsigned sptr(const void* p) {
    return (unsigned)__cvta_generic_to_shared(p);
}
__device__ __forceinline__ void ldsm4(unsigned* r, unsigned addr) {
    asm volatile("ldmatrix.sync.aligned.m8n8.x4.shared.b16 {%0,%1,%2,%3},[%4];"
                 : "=r"(r[0]), "=r"(r[1]), "=r"(r[2]), "=r"(r[3]) : "r"(addr));
}
__device__ __forceinline__ void ldsm4t(unsigned* r, unsigned addr) {
    asm volatile("ldmatrix.sync.aligned.m8n8.x4.trans.shared.b16 {%0,%1,%2,%3},[%4];"
                 : "=r"(r[0]), "=r"(r[1]), "=r"(r[2]), "=r"(r[3]) : "r"(addr));
}
__device__ __forceinline__ void mma16816(float* c, const unsigned* a, const unsigned* b) {
    asm volatile("mma.sync.aligned.m16n8k16.row.col.f32.bf16.bf16.f32 "
                 "{%0,%1,%2,%3},{%4,%5,%6,%7},{%8,%9},{%0,%1,%2,%3};"
                 : "+f"(c[0]), "+f"(c[1]), "+f"(c[2]), "+f"(c[3])
                 : "r"(a[0]), "r"(a[1]), "r"(a[2]), "r"(a[3]), "r"(b[0]), "r"(b[1]));
}
__device__ __forceinline__ uint2 cvtf4(float4 v) {
    __nv_bfloat162 lo = __float22bfloat162_rn(make_float2(v.x, v.y));
    __nv_bfloat162 hi = __float22bfloat162_rn(make_float2(v.z, v.w));
    uint2 u; u.x = *(unsigned*)&lo; u.y = *(unsigned*)&hi; return u;
}
__device__ __forceinline__ void splitf4(float4 v, uint2& H, uint2& L) {
    __nv_bfloat16 h0 = __float2bfloat16(v.x), h1 = __float2bfloat16(v.y);
    __nv_bfloat16 h2 = __float2bfloat16(v.z), h3 = __float2bfloat16(v.w);
    __nv_bfloat16 l0 = __float2bfloat16(v.x - __bfloat162float(h0));
    __nv_bfloat16 l1 = __float2bfloat16(v.y - __bfloat162float(h1));
    __nv_bfloat16 l2 = __float2bfloat16(v.z - __bfloat162float(h2));
    __nv_bfloat16 l3 = __float2bfloat16(v.w - __bfloat162float(h3));
    H.x = (unsigned)*(unsigned short*)&h0 | ((unsigned)*(unsigned short*)&h1 << 16);
    H.y = (unsigned)*(unsigned short*)&h2 | ((unsigned)*(unsigned short*)&h3 << 16);
    L.x = (unsigned)*(unsigned short*)&l0 | ((unsigned)*(unsigned short*)&l1 << 16);
    L.y = (unsigned)*(unsigned short*)&l2 | ((unsigned)*(unsigned short*)&l3 << 16);
}

// -- batched bf16 tensor-core GEMM, 128x64 tile, frag-pipelined, overlay epi --
template<int TRANSB>
__global__ void __launch_bounds__(256) gemmT_k(GPtrs p, int K, int lda, int ldb, int ldc,
                                               float alpha, int act)
{
    constexpr int BR = TRANSB ? 64 : 32;
    constexpr int BC = TRANSB ? 40 : 72;
    constexpr int AS_B = 2 * 128 * 40 * 2;
    constexpr int BS_B = 2 * BR * BC * 2;
    constexpr int CS_B = 128 * 68 * 4;
    constexpr int SM_B = (AS_B + BS_B > CS_B) ? (AS_B + BS_B) : CS_B;
    __shared__ __align__(16) char smraw[SM_B];
    typedef unsigned short ArrA[128][40];
    typedef unsigned short ArrB[BR][BC];
    ArrA* As = reinterpret_cast<ArrA*>(smraw);
    ArrB* Bs = reinterpret_cast<ArrB*>(smraw + AS_B);
    float (*Cs)[68] = reinterpret_cast<float(*)[68]>(smraw);

    const float* __restrict__ A = p.A[blockIdx.z];
    const float* __restrict__ B = p.B[blockIdx.z];
    float* __restrict__ C = p.C[blockIdx.z];
    const int bm = blockIdx.y * 128, bn = blockIdx.x * 64;
    const int t = threadIdx.x, lane = t & 31, wid = t >> 5;
    const int wy = TRANSB ? (wid >> 1) : (wid & 1);
    const int wx = TRANSB ? (wid & 1)  : (wid >> 1);

    float4 aR[4], bR[2];
    auto loadG = [&](int k0) {
        #pragma unroll
        for (int i = 0; i < 4; i++) {
            int l = t + i * 256;
            aR[i] = *(const float4*)&A[(size_t)(bm + (l >> 3)) * lda + k0 + (l & 7) * 4];
        }
        #pragma unroll
        for (int i = 0; i < 2; i++) {
            int l = t + i * 256;
            if (TRANSB)
                bR[i] = *(const float4*)&B[(size_t)(bn + (l >> 3)) * ldb + k0 + (l & 7) * 4];
            else
                bR[i] = *(const float4*)&B[(size_t)(k0 + (l >> 4)) * ldb + bn + (l & 15) * 4];
        }
    };
    auto storeS = [&](int buf) {
        #pragma unroll
        for (int i = 0; i < 4; i++) {
            int l = t + i * 256;
            *(uint2*)&As[buf][l >> 3][(l & 7) * 4] = cvtf4(aR[i]);
        }
        #pragma unroll
        for (int i = 0; i < 2; i++) {
            int l = t + i * 256;
            if (TRANSB) *(uint2*)&Bs[buf][l >> 3][(l & 7) * 4] = cvtf4(bR[i]);
            else        *(uint2*)&Bs[buf][l >> 4][(l & 15) * 4] = cvtf4(bR[i]);
        }
    };

    unsigned afr[2][2][4], bfr[2][4][2];
    auto loadFrag = [&](int c_, int ks, int slot) {
        if (TRANSB) {
            #pragma unroll
            for (int tn = 0; tn < 2; tn++) {
                int row = wy * 32 + tn * 16 + (lane & 15);
                int kof = ks + ((lane >> 4) << 3);
                ldsm4(afr[slot][tn], sptr(&As[c_][row][kof]));
            }
            #pragma unroll
            for (int g = 0; g < 2; g++) {
                int row = wx * 32 + g * 16 + ((lane >> 4) << 3) + (lane & 7);
                int kof = ks + (((lane >> 3) & 1) << 3);
                unsigned r[4];
                ldsm4(r, sptr(&Bs[c_][row][kof]));
                bfr[slot][2*g][0] = r[0]; bfr[slot][2*g][1] = r[1];
                bfr[slot][2*g+1][0] = r[2]; bfr[slot][2*g+1][1] = r[3];
            }
        } else {
            #pragma unroll
            for (int tn = 0; tn < 2; tn++) {   // opA = B^T via trans LDSM
                int krow = ks + ((lane >> 4) << 3) + (lane & 7);
                int nof  = wy * 32 + tn * 16 + (((lane >> 3) & 1) << 3);
                ldsm4t(afr[slot][tn], sptr(&Bs[c_][krow][nof]));
            }
            #pragma unroll
            for (int g = 0; g < 2; g++) {      // opB = A^T via non-trans LDSM
                int row = wx * 32 + g * 16 + ((lane >> 4) << 3) + (lane & 7);
                int kof = ks + (((lane >> 3) & 1) << 3);
                unsigned r[4];
                ldsm4(r, sptr(&As[c_][row][kof]));
                bfr[slot][2*g][0] = r[0]; bfr[slot][2*g][1] = r[1];
                bfr[slot][2*g+1][0] = r[2]; bfr[slot][2*g+1][1] = r[3];
            }
        }
    };

    float acc[2][4][4] = {};
    auto mmaAll = [&](int slot) {
        #pragma unroll
        for (int tn = 0; tn < 2; tn++)
            #pragma unroll
            for (int tb = 0; tb < 4; tb++)
                mma16816(acc[tn][tb], afr[slot][tn], bfr[slot][tb]);
    };

    loadG(0); storeS(0); __syncthreads();
    loadFrag(0, 0, 0);
    int cur = 0;
    for (int k0 = 0; k0 < K; k0 += 32) {
        const int kn = k0 + 32;
        if (kn < K) loadG(kn);
        loadFrag(cur, 16, 1);
        mmaAll(0);
        if (kn < K) storeS(cur ^ 1);
        mmaAll(1);
        __syncthreads();
        cur ^= 1;
        if (kn < K) loadFrag(cur, 0, 0);
    }

    const int g = lane >> 2, tg = lane & 3;
    #pragma unroll
    for (int tn = 0; tn < 2; tn++)
        #pragma unroll
        for (int tb = 0; tb < 4; tb++)
            #pragma unroll
            for (int r = 0; r < 4; r++) {
                int rr = wy * 32 + tn * 16 + g + ((r >> 1) << 3);
                int cc = wx * 32 + tb * 8 + 2 * tg + (r & 1);
                if (TRANSB) Cs[rr][cc] = acc[tn][tb][r];
                else        Cs[cc][rr] = acc[tn][tb][r];
            }
    __syncthreads();
    #pragma unroll
    for (int i = 0; i < 8; i++) {
        int l = t + i * 256;
        int row = l >> 4, nq = (l & 15) * 4;
        float4 v;
        float* pv = &v.x;
        #pragma unroll
        for (int j = 0; j < 4; j++) {
            float w = Cs[row][nq + j] * alpha;
            if (act) w = leakyf(w);
            pv[j] = w;
        }
        *(float4*)&C[(size_t)(bm + row) * ldc + bn + nq] = v;
    }
}

// ---- ns2 GEMM: full-split bf16 (A=hi+lo, B=hi+lo, 3 mma) -> ~1e-5 rel error -
__global__ void __launch_bounds__(256) gemmNS_k(const float* __restrict__ A,
                                                const float* __restrict__ B,
                                                float* __restrict__ C,
                                                int K, int lda, int ldb, int ldc)
{
    constexpr int AH_B = 2 * 128 * 40 * 2;
    constexpr int BH_B = 2 * 32 * 72 * 2;
    __shared__ __align__(16) char smraw[2 * AH_B + 2 * BH_B];
    typedef unsigned short ArrA[128][40];
    typedef unsigned short ArrB[32][72];
    ArrA* Ah = reinterpret_cast<ArrA*>(smraw);
    ArrA* Al = reinterpret_cast<ArrA*>(smraw + AH_B);
    ArrB* Bh = reinterpret_cast<ArrB*>(smraw + 2 * AH_B);
    ArrB* Bl = reinterpret_cast<ArrB*>(smraw + 2 * AH_B + BH_B);
    float (*Cs)[68] = reinterpret_cast<float(*)[68]>(smraw);

    const int bm = blockIdx.y * 128, bn = blockIdx.x * 64;
    const int t = threadIdx.x, lane = t & 31, wid = t >> 5;
    const int wy = wid & 1, wx = wid >> 1;

    float4 aR[4], bR[2];
    auto loadG = [&](int k0) {
        #pragma unroll
        for (int i = 0; i < 4; i++) {
            int l = t + i * 256;
            aR[i] = *(const float4*)&A[(size_t)(bm + (l >> 3)) * lda + k0 + (l & 7) * 4];
        }
        #pragma unroll
        for (int i = 0; i < 2; i++) {
            int l = t + i * 256;
            bR[i] = *(const float4*)&B[(size_t)(k0 + (l >> 4)) * ldb + bn + (l & 15) * 4];
        }
    };
    auto storeS = [&](int buf) {
        #pragma unroll
        for (int i = 0; i < 4; i++) {
            int l = t + i * 256;
            uint2 H, L; splitf4(aR[i], H, L);
            *(uint2*)&Ah[buf][l >> 3][(l & 7) * 4] = H;
            *(uint2*)&Al[buf][l >> 3][(l & 7) * 4] = L;
        }
        #pragma unroll
        for (int i = 0; i < 2; i++) {
            int l = t + i * 256;
            uint2 H, L; splitf4(bR[i], H, L);
            *(uint2*)&Bh[buf][l >> 4][(l & 15) * 4] = H;
            *(uint2*)&Bl[buf][l >> 4][(l & 15) * 4] = L;
        }
    };

    loadG(0); storeS(0); __syncthreads();

    float acc[2][4][4] = {};
    int cur = 0;
    for (int k0 = 0; k0 < K; k0 += 32) {
        const int kn = k0 + 32;
        if (kn < K) loadG(kn);
        #pragma unroll
        for (int ks = 0; ks < 32; ks += 16) {
            unsigned ah[2][4], al[2][4], bh[4][2], bl[4][2];
            #pragma unroll
            for (int tn = 0; tn < 2; tn++) {
                int krow = ks + ((lane >> 4) << 3) + (lane & 7);
                int nof  = wy * 32 + tn * 16 + (((lane >> 3) & 1) << 3);
                ldsm4t(ah[tn], sptr(&Bh[cur][krow][nof]));
                ldsm4t(al[tn], sptr(&Bl[cur][krow][nof]));
            }
            #pragma unroll
            for (int g = 0; g < 2; g++) {
                int row = wx * 32 + g * 16 + ((lane >> 4) << 3) + (lane & 7);
                int kof = ks + (((lane >> 3) & 1) << 3);
                unsigned r[4];
                ldsm4(r, sptr(&Ah[cur][row][kof]));
                bh[2*g][0] = r[0]; bh[2*g][1] = r[1];
                bh[2*g+1][0] = r[2]; bh[2*g+1][1] = r[3];
                ldsm4(r, sptr(&Al[cur][row][kof]));
                bl[2*g][0] = r[0]; bl[2*g][1] = r[1];
                bl[2*g+1][0] = r[2]; bl[2*g+1][1] = r[3];
            }
            #pragma unroll
            for (int tn = 0; tn < 2; tn++)
                #pragma unroll
                for (int tb = 0; tb < 4; tb++) {
                    mma16816(acc[tn][tb], ah[tn], bh[tb]);
                    mma16816(acc[tn][tb], ah[tn], bl[tb]);
                    mma16816(acc[tn][tb], al[tn], bh[tb]);
                }
        }
        if (kn < K) storeS(cur ^ 1);
        __syncthreads();
        cur ^= 1;
    }

    const int g = lane >> 2, tg = lane & 3;
    #pragma unroll
    for (int tn = 0; tn < 2; tn++)
        #pragma unroll
        for (int tb = 0; tb < 4; tb++)
            #pragma unroll
            for (int r = 0; r < 4; r++) {
                int rr = wy * 32 + tn * 16 + g + ((r >> 1) << 3);
                int cc = wx * 32 + tb * 8 + 2 * tg + (r & 1);
                Cs[cc][rr] = acc[tn][tb][r];
            }
    __syncthreads();
    #pragma unroll
    for (int i = 0; i < 8; i++) {
        int l = t + i * 256;
        int row = l >> 4, nq = (l & 15) * 4;
        float4 v;
        float* pv = &v.x;
        #pragma unroll
        for (int j = 0; j < 4; j++)
            pv[j] = leakyf(Cs[row][nq + j]);
        *(float4*)&C[(size_t)(bm + row) * ldc + bn + nq] = v;
    }
}

// ----- ELL build (warp per row) + absorbed scratch zeroing + x* search -------
__global__ void csrB_k(const float* __restrict__ a0, const float* __restrict__ a1)
{
    const int lb = blockIdx.y * gridDim.x + blockIdx.x;   // 0..511
    {
        int i = lb * 128 + (threadIdx.x & 127);
        if (threadIdx.x < 128) { g_hist1[i] = 0; g_hist2[i] = 0; }
        else                   { g_hist3[i] = 0; g_hist4[i] = 0; }
    }
    if (lb == 0) {
        if (threadIdx.x < 4) g_sums[threadIdx.x] = 0.0;
        if (threadIdx.x >= 4 && threadIdx.x < 12) g_meta[threadIdx.x - 4] = 0u;
        if (threadIdx.x == 12) { g_candCount = 0; g_candCount2 = 0; g_bar = 0u; }
        if (threadIdx.x == 13) {
            unsigned lo = __float_as_uint(8.0f), hi = __float_as_uint(24.0f);
            while (lo < hi) {
                unsigned mid = lo + (hi - lo) / 2;
                float x = __uint_as_float(mid);
                float p = 1.f / (1.f + expf(-x));
                if (p == 1.0f) hi = mid; else lo = mid + 1;
            }
            g_xstar = lo;
        }
    }

    const int which = blockIdx.y;
    const float* adjM = which ? a1 : a0;
    int row  = blockIdx.x * (blockDim.x >> 5) + (threadIdx.x >> 5);
    int lane = threadIdx.x & 31;
    if (row >= Nn) return;
    const float* r = adjM + (size_t)row * Nn;
    int cnt = 0;
    for (int c0 = 0; c0 < Nn; c0 += 32) {
        float v = r[c0 + lane];
        unsigned m = __ballot_sync(0xffffffffu, v != 0.f);
        if (v != 0.f) {
            int pos = cnt + __popc(m & ((1u << lane) - 1u));
            if (pos < ELLW) {
                g_cols[which][row * ELLW + pos] = c0 + lane;
                g_vals[which][row * ELLW + pos] = v;
            }
        }
        cnt += __popc(m);
    }
    if (lane == 0) g_nnz[which][row] = cnt > ELLW ? ELLW : cnt;
}

// ----------- batched SpMM: Y[row, :] = leaky(sum a_rj X[j, :]), float4 -------
__global__ void spmmB_k(SpArgs a, int C)
{
    const int b   = blockIdx.y;
    const int row = blockIdx.x;
    const int which = a.wh[b];
    const float* __restrict__ X = a.X[b];
    float* __restrict__ Y = a.Y[b];
    __shared__ int   soff[ELLW];
    __shared__ float sv[ELLW];
    const int cnt = g_nnz[which][row];
    const int t = threadIdx.x;
    if (t < ELLW && t < cnt) {
        soff[t] = g_cols[which][row * ELLW + t] * C;
        sv[t]   = g_vals[which][row * ELLW + t];
    }
    __syncthreads();
    const int c = t * 4;
    float4 acc = {0.f, 0.f, 0.f, 0.f};
    #pragma unroll 8
    for (int k = 0; k < cnt; k++) {
        float4 xv = *(const float4*)&X[soff[k] + c];
        float s = sv[k];
        acc.x += s * xv.x; acc.y += s * xv.y;
        acc.z += s * xv.z; acc.w += s * xv.w;
    }
    float4 o = {leakyf(acc.x), leakyf(acc.y), leakyf(acc.z), leakyf(acc.w)};
    *(float4*)&Y[(size_t)row * C + c] = o;
}

// ------------------------- softmax over rows of 256 --------------------------
__global__ void softmax_k(float* __restrict__ s)
{
    const int row = blockIdx.x;
    float* p = s + (size_t)row * 256;
    const int t = threadIdx.x;
    __shared__ float red[256];
    float v = p[t];
    red[t] = v; __syncthreads();
    for (int st = 128; st > 0; st >>= 1) { if (t < st) red[t] = fmaxf(red[t], red[t + st]); __syncthreads(); }
    float mx = red[0]; __syncthreads();
    float e = expf(v - mx);
    red[t] = e; __syncthreads();
    for (int st = 128; st > 0; st >>= 1) { if (t < st) red[t] += red[t + st]; __syncthreads(); }
    p[t] = e / red[0];
}

// --- fused: z = eps*exp(0.5*lv)+mu (split to bf16 hi/lo) AND KLD reduction ---
__global__ void zkld_k(const float* __restrict__ eps)
{
    const int i = blockIdx.x * blockDim.x + threadIdx.x;
    float mupo = g_mu[i], lvpo = g_lv[i];
    float zv = eps[i] * expf(0.5f * lvpo) + mupo;
    __nv_bfloat16 h = __float2bfloat16(zv);
    __nv_bfloat16 l = __float2bfloat16(zv - __bfloat162float(h));
    g_zhi[i] = *(unsigned short*)&h;
    g_zlo[i] = *(unsigned short*)&l;
    float mupr = g_mupr[i], lvpr = g_lvpr[i];
    float d = mupr - mupo;
    float term = d * d * expf(-lvpr) + expf(lvpo - lvpr) - 1.f - (lvpo - lvpr);
    __shared__ float red[256];
    const int t = threadIdx.x;
    red[t] = term; __syncthreads();
    for (int st = 128; st > 0; st >>= 1) { if (t < st) red[t] += red[t + st]; __syncthreads(); }
    if (t == 0) atomicAdd(&g_sums[3], (double)red[0]);
}

// --- decoder: x = z z^T, SYMMETRIC — only tiles touching j >= i are computed.
//     BCE sums use x[i][j]==x[j][i]: off-diag weight (L_ij + L_ji), diag once.
__global__ void __launch_bounds__(256) decoder_k(const float* __restrict__ labels)
{
    const int bi = blockIdx.y * 128, bj = blockIdx.x * 64;
    if (bj + 64 <= bi) return;          // tile strictly below diagonal: skip
    __shared__ unsigned short Zih[2][128][40];
    __shared__ unsigned short Zil[2][128][40];
    __shared__ unsigned short Zjh[2][64][40];
    __shared__ unsigned short Zjl[2][64][40];
    const int t = threadIdx.x, lane = t & 31, wid = t >> 5;
    const int wy = wid >> 1, wx = wid & 1;
    const float xstar = __uint_as_float(g_xstar);

    uint4 ih[2], il[2], jh, jl;
    auto loadG = [&](int k0) {
        #pragma unroll
        for (int i = 0; i < 2; i++) {
            int l = t + i * 256;
            int row = l >> 2, c8 = (l & 3) * 8;
            ih[i] = *(const uint4*)&g_zhi[(size_t)(bi + row) * H2d + k0 + c8];
            il[i] = *(const uint4*)&g_zlo[(size_t)(bi + row) * H2d + k0 + c8];
        }
        int row = t >> 2, c8 = (t & 3) * 8;
        jh = *(const uint4*)&g_zhi[(size_t)(bj + row) * H2d + k0 + c8];
        jl = *(const uint4*)&g_zlo[(size_t)(bj + row) * H2d + k0 + c8];
    };
    auto storeS = [&](int buf) {
        #pragma unroll
        for (int i = 0; i < 2; i++) {
            int l = t + i * 256;
            int row = l >> 2, c8 = (l & 3) * 8;
            *(uint4*)&Zih[buf][row][c8] = ih[i];
            *(uint4*)&Zil[buf][row][c8] = il[i];
        }
        int row = t >> 2, c8 = (t & 3) * 8;
        *(uint4*)&Zjh[buf][row][c8] = jh;
        *(uint4*)&Zjl[buf][row][c8] = jl;
    };

    loadG(0); storeS(0); __syncthreads();

    float acc[2][4][4] = {};
    int cur = 0;
    for (int k0 = 0; k0 < H2d; k0 += 32) {
        const int kn = k0 + 32;
        if (kn < H2d) loadG(kn);
        #pragma unroll
        for (int ks = 0; ks < 32; ks += 16) {
            unsigned ah[2][4], al[2][4], bh[4][2], bl[4][2];
            #pragma unroll
            for (int tn = 0; tn < 2; tn++) {
                int row = wy * 32 + tn * 16 + (lane & 15);
                int kof = ks + ((lane >> 4) << 3);
                ldsm4(ah[tn], sptr(&Zih[cur][row][kof]));
                ldsm4(al[tn], sptr(&Zil[cur][row][kof]));
            }
            #pragma unroll
            for (int g = 0; g < 2; g++) {
                int row = wx * 32 + g * 16 + ((lane >> 4) << 3) + (lane & 7);
                int kof = ks + (((lane >> 3) & 1) << 3);
                unsigned r[4];
                ldsm4(r, sptr(&Zjh[cur][row][kof]));
                bh[2*g][0] = r[0]; bh[2*g][1] = r[1];
                bh[2*g+1][0] = r[2]; bh[2*g+1][1] = r[3];
                ldsm4(r, sptr(&Zjl[cur][row][kof]));
                bl[2*g][0] = r[0]; bl[2*g][1] = r[1];
                bl[2*g+1][0] = r[2]; bl[2*g+1][1] = r[3];
            }
            #pragma unroll
            for (int tn = 0; tn < 2; tn++)
                #pragma unroll
                for (int tb = 0; tb < 4; tb++) {
                    mma16816(acc[tn][tb], ah[tn], bh[tb]);
                    mma16816(acc[tn][tb], ah[tn], bl[tb]);
                    mma16816(acc[tn][tb], al[tn], bh[tb]);
                }
        }
        if (kn < H2d) storeS(cur ^ 1);
        __syncthreads();
        cur ^= 1;
    }

    // ---- epilogue pass 1: upper-triangle keys + symmetric bce sums ----
    const int gq = lane >> 2, tg = lane & 3;
    float s1 = 0.f, s2 = 0.f, ls = 0.f;
    int myCnt = 0;
    #pragma unroll
    for (int tn = 0; tn < 2; tn++)
        #pragma unroll
        for (int tb = 0; tb < 4; tb++)
            #pragma unroll
            for (int r = 0; r < 4; r++) {
                int gi = bi + wy * 32 + tn * 16 + gq + ((r >> 1) << 3);
                int gj = bj + wx * 32 + tb * 8 + 2 * tg + (r & 1);
                if (gj < gi) continue;
                float x = acc[tn][tb][r];
                bool sat = (x >= xstar);
                float texp = __expf(-x);
                float pa = __fdividef(1.f, 1.f + texp);
                float tt = __expf(-pa);
                float u  = __logf(1.f + tt);
                if (gj > gi) {
                    float L1 = labels[(size_t)gi * Nn + gj];
                    float L2 = labels[(size_t)gj * Nn + gi];
                    float w = L1 + L2;
                    s1 += w * (-u);
                    s2 += (2.f - w) * (-(pa + u));
                    ls += w;
                    unsigned pb = __float_as_uint(pa);
                    pb = sat ? 0x3F800000u : (pb >= 0x3F800000u ? 0x3F7FFFFFu : pb);
                    g_keys[(size_t)gi * Nn + gj] = pb;
                    myCnt += sat ? 1 : 0;
                } else {
                    float L = labels[(size_t)gi * Nn + gi];
                    s1 += L * (-u);
                    s2 += (1.f - L) * (-(pa + u));
                    ls += L;
                }
            }

    __shared__ int scnt[256];
    __shared__ int sbase;
    scnt[t] = myCnt; __syncthreads();
    #pragma unroll
    for (int off = 1; off < 256; off <<= 1) {
        int v = (t >= off) ? scnt[t - off] : 0;
        __syncthreads();
        scnt[t] += v;
        __syncthreads();
    }
    if (t == 255) sbase = atomicAdd(&g_candCount, scnt[255]);
    __syncthreads();
    int wpos = sbase + scnt[t] - myCnt;

    if (myCnt > 0) {
        #pragma unroll
        for (int tn = 0; tn < 2; tn++)
            #pragma unroll
            for (int tb = 0; tb < 4; tb++)
                #pragma unroll
                for (int r = 0; r < 4; r++) {
                    int gi = bi + wy * 32 + tn * 16 + gq + ((r >> 1) << 3);
                    int gj = bj + wx * 32 + tb * 8 + 2 * tg + (r & 1);
                    if (gj > gi && acc[tn][tb][r] >= xstar) {
                        unsigned idx = (unsigned)(gi * Nn + gj);
                        if (wpos < CAPBIG)
                            g_candBig[wpos] = (0x3F800000ull << 32)
                                            | (0xFFFFFFFFu - idx);
                        wpos++;
                    }
                }
    }

    __shared__ float red[256];
    red[t] = s1; __syncthreads();
    for (int st = 128; st > 0; st >>= 1) { if (t < st) red[t] += red[t + st]; __syncthreads(); }
    float bs1 = red[0]; __syncthreads();
    red[t] = s2; __syncthreads();
    for (int st = 128; st > 0; st >>= 1) { if (t < st) red[t] += red[t + st]; __syncthreads(); }
    float bs2 = red[0]; __syncthreads();
    red[t] = ls; __syncthreads();
    for (int st = 128; st > 0; st >>= 1) { if (t < st) red[t] += red[t + st]; __syncthreads(); }
    if (t == 0) {
        atomicAdd(&g_sums[1], (double)bs1);
        atomicAdd(&g_sums[2], (double)bs2);
        atomicAdd(&g_sums[0], (double)red[0]);
    }
}

// --- fused topk tail + select + gather + scalars ------------------------------
__global__ void __launch_bounds__(256) topkFused_k(float* __restrict__ out)
{
    const int lane = threadIdx.x & 31;
    const int stride = gridDim.x * blockDim.x;
    __shared__ unsigned Ssum[256];
    int ph = 0;
    auto gsync = [&]() {
        __syncthreads();
        if (threadIdx.x == 0) {
            __threadfence();
            atomicAdd(&g_bar, 1u);
            ph++;
            while (atomicAdd(&g_bar, 0u) < (unsigned)(ph * gridDim.x)) {}
            __threadfence();
        }
        __syncthreads();
    };

    if (blockIdx.x == 0 && threadIdx.x == 0) {
        if (g_candCount >= MAXK) {
            g_meta[0] = 0x3F80u; g_meta[1] = 0u;
            g_meta[2] = 0x3F800000u; g_meta[3] = 0u;
            g_meta[7] = 1u;
        } else {
            g_meta[7] = 0u; g_candCount = 0;
        }
    }
    gsync();
    const unsigned ok = g_meta[7];

    if (!ok) {
        for (int base = blockIdx.x * blockDim.x; base < Nn * Nn; base += stride) {
            int i = base + threadIdx.x;
            unsigned key = g_keys[i];
            unsigned m = __ballot_sync(0xffffffffu, key != 0u);
            if (key != 0u) {
                unsigned bin = key >> 16;
                unsigned peers = __match_any_sync(m, bin);
                if ((unsigned)(__ffs(peers) - 1) == (unsigned)lane)
                    atomicAdd(&g_hist1[bin], (unsigned)__popc(peers));
            }
        }
        gsync();
        if (blockIdx.x == 0) {
            const int t = threadIdx.x;
            const int base = t * 256;
            unsigned local = 0;
            for (int i = 0; i < 256; i++) local += g_hist1[base + i];
            Ssum[t] = local; __syncthreads();
            for (int off = 1; off < 256; off <<= 1) {
                unsigned v = (t + off < 256) ? Ssum[t + off] : 0u;
                __syncthreads();
                Ssum[t] += v;
                __syncthreads();
            }
            unsigned cum = Ssum[t] - local;
            for (int b = base + 255; b >= base; b--) {
                unsigned h = g_hist1[b];
                if (cum < MAXK && cum + h >= MAXK) { g_meta[0] = (unsigned)b; g_meta[1] = cum; }
                cum += h;
            }
        }
        gsync();
        {
            const unsigned P1 = g_meta[0];
            for (int base = blockIdx.x * blockDim.x; base < Nn * Nn; base += stride) {
                int i = base + threadIdx.x;
                unsigned key = g_keys[i];
                bool take = (key != 0u) && ((key >> 16) >= P1);
                unsigned m = __ballot_sync(0xffffffffu, take);
                if (m) {
                    int leader = __ffs(m) - 1;
                    int pbase = 0;
                    if (lane == leader) pbase = atomicAdd(&g_candCount, __popc(m));
                    pbase = __shfl_sync(0xffffffffu, pbase, leader);
                    if (take) {
                        int pos = pbase + __popc(m & ((1u << lane) - 1u));
                        if (pos < CAPBIG)
                            g_candBig[pos] = ((unsigned long long)key << 32)
                                           | (unsigned)(0xFFFFFFFFu - (unsigned)i);
                    }
                }
            }
        }
        gsync();
        {
            const int cnt2 = g_candCount < CAPBIG ? g_candCount : CAPBIG;
            const unsigned P1 = g_meta[0];
            for (int base = blockIdx.x * blockDim.x; base < cnt2; base += stride) {
                int i = base + threadIdx.x;
                unsigned key = 0u;
                if (i < cnt2) key = (unsigned)(g_candBig[i] >> 32);
                bool on = (i < cnt2) && ((key >> 16) == P1);
                unsigned m = __ballot_sync(0xffffffffu, on);
                if (on) {
                    unsigned bin = key & 0xFFFFu;
                    unsigned peers = __match_any_sync(m, bin);
                    if ((unsigned)(__ffs(peers) - 1) == (unsigned)lane)
                        atomicAdd(&g_hist2[bin], (unsigned)__popc(peers));
                }
            }
        }
        gsync();
        if (blockIdx.x == 0) {
            const int t = threadIdx.x;
            const int base = t * 256;
            const unsigned cA1 = g_meta[1];
            const unsigned P1 = g_meta[0];
            unsigned local = 0;
            for (int i = 0; i < 256; i++) local += g_hist2[base + i];
            Ssum[t] = local; __syncthreads();
            for (int off = 1; off < 256; off <<= 1) {
                unsigned v = (t + off < 256) ? Ssum[t + off] : 0u;
                __syncthreads();
                Ssum[t] += v;
                __syncthreads();
            }
            unsigned cum = cA1 + Ssum[t] - local;
            for (int b = base + 255; b >= base; b--) {
                unsigned h = g_hist2[b];
                if (cum < MAXK && cum + h >= MAXK) {
                    g_meta[2] = (P1 << 16) | (unsigned)b;
                    g_meta[3] = cum;
                }
                cum += h;
            }
        }
        gsync();
    }

    const int count = g_candCount < CAPBIG ? g_candCount : CAPBIG;

    {
        const unsigned TH = g_meta[2];
        for (int base = blockIdx.x * blockDim.x; base < count; base += stride) {
            int i = base + threadIdx.x;
            unsigned long long c = 0ull;
            if (i < count) c = g_candBig[i];
            bool on = (i < count) && ((unsigned)(c >> 32) == TH);
            unsigned m = __ballot_sync(0xffffffffu, on);
            if (on) {
                unsigned bin = ((unsigned)c) >> 16;
                unsigned peers = __match_any_sync(m, bin);
                if ((unsigned)(__ffs(peers) - 1) == (unsigned)lane)
                    atomicAdd(&g_hist3[bin], (unsigned)__popc(peers));
            }
        }
    }
    gsync();
    if (blockIdx.x == 0) {
        const int t = threadIdx.x;
        const int base = t * 256;
        const unsigned need = MAXK - g_meta[3];
        unsigned local = 0;
        for (int i = 0; i < 256; i++) local += g_hist3[base + i];
        Ssum[t] = local; __syncthreads();
        for (int off = 1; off < 256; off <<= 1) {
            unsigned v = (t + off < 256) ? Ssum[t + off] : 0u;
            __syncthreads();
            Ssum[t] += v;
            __syncthreads();
        }
        unsigned cum = Ssum[t] - local;
        for (int b = base + 255; b >= base; b--) {
            unsigned h = g_hist3[b];
            if (cum < need && cum + h >= need) { g_meta[4] = (unsigned)b; g_meta[5] = cum; }
            cum += h;
        }
    }
    gsync();
    {
        const unsigned TH = g_meta[2];
        const unsigned S1 = g_meta[4];
        for (int base = blockIdx.x * blockDim.x; base < count; base += stride) {
            int i = base + threadIdx.x;
            unsigned long long c = 0ull;
            if (i < count) c = g_candBig[i];
            unsigned sec = (unsigned)c;
            bool on = (i < count) && ((unsigned)(c >> 32) == TH) && ((sec >> 16) == S1);
            unsigned m = __ballot_sync(0xffffffffu, on);
            if (on) {
                unsigned bin = sec & 0xFFFFu;
                unsigned peers = __match_any_sync(m, bin);
                if ((unsigned)(__ffs(peers) - 1) == (unsigned)lane)
                    atomicAdd(&g_hist4[bin], (unsigned)__popc(peers));
            }
        }
    }
    gsync();
    if (blockIdx.x == 0) {
        const int t = threadIdx.x;
        const int base = t * 256;
        const unsigned need = MAXK - g_meta[3];
        const unsigned cA = g_meta[5];
        const unsigned S1 = g_meta[4];
        unsigned local = 0;
        for (int i = 0; i < 256; i++) local += g_hist4[base + i];
        Ssum[t] = local; __syncthreads();
        for (int off = 1; off < 256; off <<= 1) {
            unsigned v = (t + off < 256) ? Ssum[t + off] : 0u;
            __syncthreads();
            Ssum[t] += v;
            __syncthreads();
        }
        unsigned cum = cA + Ssum[t] - local;
        for (int b = base + 255; b >= base; b--) {
            unsigned h = g_hist4[b];
            if (cum < need && cum + h >= need) g_meta[6] = (S1 << 16) | (unsigned)b;
            cum += h;
        }
    }
    gsync();
    {
        const unsigned TH = g_meta[2];
        const unsigned SECTH = g_meta[6];
        for (int base = blockIdx.x * blockDim.x; base < count; base += stride) {
            int i = base + threadIdx.x;
            unsigned long long c = 0ull;
            if (i < count) c = g_candBig[i];
            unsigned key = (unsigned)(c >> 32);
            unsigned sec = (unsigned)c;
            bool take = (i < count) && ((key > TH) || (key == TH && sec >= SECTH));
            unsigned m = __ballot_sync(0xffffffffu, take);
            if (m) {
                int leader = __ffs(m) - 1;
                int pbase = 0;
                if (lane == leader) pbase = atomicAdd(&g_candCount2, __popc(m));
                pbase = __shfl_sync(0xffffffffu, pbase, leader);
                if (take) {
                    int pos = pbase + __popc(m & ((1u << lane) - 1u));
                    if (pos < CAP) g_cand[pos] = c;
                }
            }
        }
    }
    gsync();
    if (blockIdx.x == 0) {
        int C = g_candCount2; if (C > CAP) C = CAP;
        const int t = threadIdx.x;
        __shared__ unsigned long long sc[CAP];
        for (int c = t; c < C; c += 256) sc[c] = g_cand[c];
        __syncthreads();
        for (int c = t; c < C; c += 256) {
            unsigned long long me = sc[c];
            int rank = 0;
            for (int o = 0; o < C; o++) rank += (sc[o] > me);
            if (rank < MAXK) {
                unsigned lo = (unsigned)(me & 0xFFFFFFFFu);
                g_sel[rank] = (int)(0xFFFFFFFFu - lo);
            }
        }
    }
    gsync();
    for (int e = blockIdx.x * blockDim.x + threadIdx.x; e < MAXK * H2d; e += stride) {
        int r = e >> 8, c = e & 255;
        int idx = g_sel[r];
        int a = idx >> 11, b = idx & 2047;
        out[e] = g_ns2[(size_t)a * H2d + c] + g_ns2[(size_t)b * H2d + c];
    }
    if (blockIdx.x == 0) {
        for (int i = threadIdx.x; i < MAXK; i += 256) out[MAXK * H2d + i] = 0.f;
        if (threadIdx.x == 0) {
            double sLab = g_sums[0], s1 = g_sums[1], s2 = g_sums[2], kls = g_sums[3];
            double n = (double)Nn, n2 = n * n;
            double pw   = (n2 - sLab + n) / (sLab - n + 0.01);
            double norm = n2 / (n2 - sLab + n);
            double recons = norm * (-(pw * s1 + s2) / n2);
            double kld = 0.5 * kls / n2;
            out[MAXK * H2d + MAXK]     = (float)recons;
            out[MAXK * H2d + MAXK + 1] = (float)kld;
        }
    }
}

// ------------------------- host launcher --------------------------------------
template <typename T>
static float* symaddr(T& sym) { void* p = nullptr; cudaGetSymbolAddress(&p, sym); return (float*)p; }

extern "C" void kernel_launch(void* const* d_in, const int* in_sizes, int n_in,
                              void* d_out, int out_size)
{
    const float* ns_emb = (const float*)d_in[0];
    const float* adj    = (const float*)d_in[1];
    const float* adjp   = (const float*)d_in[2];
    const float* cond   = (const float*)d_in[3];
    const float* labels = (const float*)d_in[4];
    const float* eps    = (const float*)d_in[5];
    const float* W_map  = (const float*)d_in[6];
    const float* W[14];
    for (int i = 0; i < 14; i++) W[i] = (const float*)d_in[7 + i];
    float* out = (float*)d_out;

    float* Sb   = symaddr(g_S);
    float* Hidb = symaddr(g_Hid);
    float* Qb   = symaddr(g_Q);
    float* Kbb  = symaddr(g_Kb);
    float* Vbb  = symaddr(g_Vb);
    float* attb = symaddr(g_att);
    float* Ob   = symaddr(g_O);
    float* Mhb  = symaddr(g_Mh);
    float* Tb   = symaddr(g_T);
    float* mu   = symaddr(g_mu);
    float* lv   = symaddr(g_lv);
    float* mupr = symaddr(g_mupr);
    float* lvpr = symaddr(g_lvpr);
    float* ns2  = symaddr(g_ns2);

    auto S   = [&](int e){ return Sb   + (size_t)e * Nn  * H1d; };
    auto Hid = [&](int e){ return Hidb + (size_t)e * Nn  * H1d; };
    auto Q   = [&](int e){ return Qb   + (size_t)e * Nn  * H1d; };
    auto Kb  = [&](int e){ return Kbb  + (size_t)e * LCd * H1d; };
    auto Vb  = [&](int e){ return Vbb  + (size_t)e * LCd * H1d; };
    auto ATT = [&](int b){ return attb + (size_t)b * Nn  * LCd; };
    auto O   = [&](int e){ return Ob   + (size_t)e * Nn  * H1d; };
    auto Mh  = [&](int e){ return Mhb  + (size_t)e * Nn  * H1d; };
    auto T   = [&](int b){ return Tb   + (size_t)b * Nn  * H2d; };

    auto gemm = [&](GPtrs p, int bat, int M, int N, int K,
                    int lda, int ldb, int ldc, float alpha, int transB, int act) {
        dim3 grd(N / 64, M / 128, bat);
        if (transB) gemmT_k<1><<<grd, 256>>>(p, K, lda, ldb, ldc, alpha, act);
        else        gemmT_k<0><<<grd, 256>>>(p, K, lda, ldb, ldc, alpha, act);
    };

    csrB_k<<<dim3(Nn / 8, 2), 256>>>(adj, adjp);

    // S[e] = leaky(ns_emb @ W_hid[e])
    { GPtrs p = {{ns_emb, ns_emb}, {W[0], W[7]}, {S(0), S(1)}};
      gemm(p, 2, Nn, H1d, FIN, FIN, H1d, H1d, 1.f, 0, 1); }
    // Hid[e] = adj[e] (sparse) @ S[e]
    { SpArgs a = {{S(0), S(1)}, {Hid(0), Hid(1)}, {0, 1}};
      spmmB_k<<<dim3(Nn, 2), H1d / 4>>>(a, H1d); }
    // Q[e] = Hid[e] @ Wq[e]
    { GPtrs p = {{Hid(0), Hid(1)}, {W[1], W[8]}, {Q(0), Q(1)}};
      gemm(p, 2, Nn, H1d, H1d, H1d, H1d, H1d, 1.f, 0, 0); }
    // K/V for both encoders (M=256)
    { GPtrs p = {{cond, cond, cond, cond}, {W[2], W[3], W[9], W[10]},
                 {Kb(0), Vb(0), Kb(1), Vb(1)}};
      gemm(p, 4, LCd, H1d, FIN, FIN, H1d, H1d, 1.f, 0, 0); }
    // att[b=(e,h)] = Q[e]_h @ Kb[e]_h^T / 16
    { GPtrs p = {{Q(0), Q(0) + 256, Q(1), Q(1) + 256},
                 {Kb(0), Kb(0) + 256, Kb(1), Kb(1) + 256},
                 {ATT(0), ATT(1), ATT(2), ATT(3)}};
      gemm(p, 4, Nn, LCd, 256, H1d, H1d, LCd, 1.f / 16.f, 1, 0); }
    softmax_k<<<4 * Nn, 256>>>(attb);
    // O[e]_h = att[b] @ Vb[e]_h
    { GPtrs p = {{ATT(0), ATT(1), ATT(2), ATT(3)},
                 {Vb(0), Vb(0) + 256, Vb(1), Vb(1) + 256},
                 {O(0), O(0) + 256, O(1), O(1) + 256}};
      gemm(p, 4, Nn, 256, LCd, LCd, H1d, H1d, 1.f, 0, 0); }
    // Mh[e] = O[e] @ Wo[e]
    { GPtrs p = {{O(0), O(1)}, {W[4], W[11]}, {Mh(0), Mh(1)}};
      gemm(p, 2, Nn, H1d, H1d, H1d, H1d, H1d, 1.f, 0, 0); }
    // T[0..3] = leaky(Mh[e] @ {Wmu[e], Wvar[e]})
    { GPtrs p = {{Mh(0), Mh(0), Mh(1), Mh(1)}, {W[5], W[6], W[12], W[13]},
                 {T(0), T(1), T(2), T(3)}};
      gemm(p, 4, Nn, H2d, H1d, H1d, H2d, H2d, 1.f, 0, 1); }
    // {mu, lv, mupr, lvpr} = adj[e] (sparse) @ T[b]
    { SpArgs a = {{T(0), T(1), T(2), T(3)}, {mu, lv, mupr, lvpr}, {0, 0, 1, 1}};
      spmmB_k<<<dim3(Nn, 4), H2d / 4>>>(a, H2d); }

    zkld_k<<<Nn * H2d / 256, 256>>>(eps);
    gemmNS_k<<<dim3(H2d / 64, Nn / 128), 256>>>(ns_emb, W_map, ns2, FIN, FIN, H2d, H2d);

    decoder_k<<<dim3(Nn / 64, Nn / 128), 256>>>(labels);
    topkFused_k<<<NBLK, 256>>>(out);

    (void)in_sizes; (void)n_in; (void)out_size;
}